// round 11
// baseline (speedup 1.0000x reference)
#include <cuda_runtime.h>
#include <math.h>
#include <stdint.h>

#define BB    16
#define LSEQ  4096
#define DDIM  256
#define NIN   768
#define NF    4096
#define NFH   2048
#define KSTRIDE 4104
#define PI_F  3.14159265358979323846f

// ---------------- scratch ----------------------------------------------------
__device__ float  g_WinT [DDIM * NIN];                 // tf32-rounded
__device__ float  g_WoutT[DDIM * DDIM];                // tf32-rounded
__device__ float  g_kfilt[DDIM * LSEQ];
__device__ float2 g_Kf   [DDIM * KSTRIDE];
__device__ float  g_ur   [(size_t)BB * LSEQ * DDIM];   // tf32-rounded u
__device__ float  g_x0t  [(size_t)BB * DDIM * LSEQ];
__device__ float  g_vint [(size_t)BB * DDIM * LSEQ];
__device__ float2 g_tw1  [1024];
__device__ float2 g_twu  [2049];

__device__ __forceinline__ float2 cmul(float2 a, float2 b) {
    return make_float2(a.x * b.x - a.y * b.y, a.x * b.y + a.y * b.x);
}

#define CPA16(dst_u32, src_ptr) \
    asm volatile("cp.async.cg.shared.global [%0], [%1], 16;" :: "r"(dst_u32), "l"(src_ptr))
#define CPA_COMMIT() asm volatile("cp.async.commit_group;")

#define MMA_TF32(C, A, B) \
    asm volatile("mma.sync.aligned.m16n8k8.row.col.f32.tf32.tf32.f32 " \
        "{%0,%1,%2,%3}, {%4,%5,%6,%7}, {%8,%9}, {%0,%1,%2,%3};" \
        : "+f"(C.x), "+f"(C.y), "+f"(C.z), "+f"(C.w) \
        : "r"(A[0]), "r"(A[1]), "r"(A[2]), "r"(A[3]), "r"(B[0]), "r"(B[1]))

__device__ __forceinline__ uint32_t f2tf32(float v) {
    uint32_t r;
    asm("cvt.rna.tf32.f32 %0, %1;" : "=r"(r) : "f"(v));
    return r;
}
__device__ __forceinline__ float tf32r(float v) { return __uint_as_float(f2tf32(v)); }

// ---------------- K0: transpose + tf32-round weights + twiddles --------------
__global__ void k_transpose(const float* __restrict__ Win, const float* __restrict__ Wout) {
    int i = blockIdx.x * blockDim.x + threadIdx.x;
    if (i < DDIM * NIN) {
        int d = i / NIN, e = i % NIN;
        g_WinT[i] = tf32r(Win[e * DDIM + d]);
    }
    int j = i - DDIM * NIN;
    if (j >= 0 && j < DDIM * DDIM) {
        int d = j / DDIM, n = j % DDIM;
        g_WoutT[j] = tf32r(Wout[n * DDIM + d]);
    }
    if (i < 1024) {
        float ang = -2.0f * PI_F * (float)i / (float)NF;
        float sn, cs; sincosf(ang, &sn, &cs);
        g_tw1[i] = make_float2(cs, sn);
    }
    if (i < 2049) {
        float ang = PI_F * (float)i / (float)NF;
        float sn, cs; sincosf(ang, &sn, &cs);
        g_twu[i] = make_float2(cs, sn);
    }
}

// ---------------- K0b: tf32-round u ------------------------------------------
__global__ void k_roundu(const float4* __restrict__ u) {
    size_t i = (size_t)blockIdx.x * 256 + threadIdx.x;   // grid 16384
    float4 v = u[i];
    v.x = tf32r(v.x); v.y = tf32r(v.y); v.z = tf32r(v.z); v.w = tf32r(v.w);
    ((float4*)g_ur)[i] = v;
}

// ---------------- K1: implicit filter MLP (4 l per block) --------------------
__global__ void k_filter(const float* __restrict__ w1, const float* __restrict__ b1,
                         const float* __restrict__ fr,
                         const float* __restrict__ w2, const float* __restrict__ b2,
                         const float* __restrict__ w3, const float* __restrict__ b3,
                         const float* __restrict__ w4) {
    int lq = threadIdx.x >> 6;       // 0..3
    int j  = threadIdx.x & 63;
    int l  = blockIdx.x * 4 + lq;
    __shared__ float hA[4][64], hB[4][64];

    float t    = (float)l * (1.0f / (float)(LSEQ - 1));
    float wang = 2.0f * PI_F * (float)l / (float)LSEQ;
    const float f0 = 1e-4f;
    float z0 = t, z1 = cosf(f0 * wang), z2 = -sinf(f0 * wang);

    float a = z0 * w1[j * 3 + 0] + z1 * w1[j * 3 + 1] + z2 * w1[j * 3 + 2] + b1[j];
    hA[lq][j] = sinf(fr[j] * a);
    __syncthreads();

    float s = b2[j];
    #pragma unroll
    for (int i = 0; i < 64; i++) s += hA[lq][i] * w2[j * 64 + i];
    hB[lq][j] = sinf(fr[j] * s);
    __syncthreads();

    s = b3[j];
    #pragma unroll
    for (int i = 0; i < 64; i++) s += hB[lq][i] * w3[j * 64 + i];
    float hv = sinf(fr[j] * s);
    __syncthreads();
    hA[lq][j] = hv;
    __syncthreads();

    const float min_d = logf(0.01f) / 1.5f;
    const float max_d = logf(0.01f) / 0.3f;
    #pragma unroll
    for (int r = 0; r < 4; r++) {
        int d = j * 4 + r;
        float s4 = 0.f;
        #pragma unroll
        for (int i = 0; i < 64; i++) s4 += hA[lq][i] * w4[d * 64 + i];
        float delta = fabsf(min_d + (max_d - min_d) * ((float)d / (float)(DDIM - 1)));
        g_kfilt[d * LSEQ + l] = s4 * expf(-t * delta);
    }
}

// ---------------- radix-16 Stockham FFT: 4096 pt, 3 stages, 256 thr ----------
#define SWIZ(a) ((a) ^ (((a) >> 4) & 15))

template<int INV>
__device__ __forceinline__ void bfly4(float2 s0, float2 s1, float2 s2, float2 s3,
                                      float2& y0, float2& y1, float2& y2, float2& y3) {
    float u0x = s0.x + s2.x, u0y = s0.y + s2.y;
    float u1x = s0.x - s2.x, u1y = s0.y - s2.y;
    float u2x = s1.x + s3.x, u2y = s1.y + s3.y;
    float u3x = s1.x - s3.x, u3y = s1.y - s3.y;
    y0 = make_float2(u0x + u2x, u0y + u2y);
    y2 = make_float2(u0x - u2x, u0y - u2y);
    if (INV) {
        y1 = make_float2(u1x - u3y, u1y + u3x);
        y3 = make_float2(u1x + u3y, u1y - u3x);
    } else {
        y1 = make_float2(u1x + u3y, u1y - u3x);
        y3 = make_float2(u1x - u3y, u1y + u3x);
    }
}

template<int INV>
__device__ __forceinline__ void fft16(float2* __restrict__ buf0, float2* __restrict__ buf1,
                                      const float2* __restrict__ tw, int tid) {
    const float C8 = 0.9238795325112867f;
    const float S8 = 0.3826834323650898f;
    const float C4 = 0.7071067811865476f;
    const float sg = INV ? 1.0f : -1.0f;
    const float2 F1 = make_float2( C8, sg * S8);
    const float2 F2 = make_float2( C4, sg * C4);
    const float2 F3 = make_float2( S8, sg * C8);
    const float2 F4 = make_float2(0.f, sg * 1.f);
    const float2 F6 = make_float2(-C4, sg * C4);
    const float2 F9 = make_float2(-C8, -sg * S8);

    #pragma unroll
    for (int s = 0; s < 3; s++) {
        const int m = (s == 0) ? 1 : (s == 1) ? 16 : 256;
        const float2* src = (s == 1) ? buf1 : buf0;
        float2*       dst = (s == 1) ? buf0 : buf1;
        const bool swR = (s == 1), swW = (s == 0);

        int k  = tid & (m - 1);
        int bq = tid - k;

        float2 X[4][4];
        #pragma unroll
        for (int j = 0; j < 4; j++)
            #pragma unroll
            for (int r = 0; r < 4; r++) {
                int a = tid + 256 * r + 1024 * j;
                X[r][j] = src[swR ? SWIZ(a) : a];
            }

        float2 wa1 = tw[bq]; if (INV) wa1.y = -wa1.y;
        float2 wa2 = cmul(wa1, wa1);
        float2 wa3 = cmul(wa2, wa1);
        float2 wb1 = cmul(wa2, wa2);
        float2 wb2 = cmul(wb1, wb1);
        float2 wb3 = cmul(wb2, wb1);

        float2 z[4][4];
        #pragma unroll
        for (int r = 0; r < 4; r++) {
            float2 y0, y1, y2, y3;
            bfly4<INV>(X[r][0], X[r][1], X[r][2], X[r][3], y0, y1, y2, y3);
            if (r == 1) { y1 = cmul(F1, y1); y2 = cmul(F2, y2); y3 = cmul(F3, y3); }
            if (r == 2) { y1 = cmul(F2, y1); y2 = cmul(F4, y2); y3 = cmul(F6, y3); }
            if (r == 3) { y1 = cmul(F3, y1); y2 = cmul(F6, y2); y3 = cmul(F9, y3); }
            z[r][0] = y0;
            z[r][1] = cmul(wa1, y1);
            z[r][2] = cmul(wa2, y2);
            z[r][3] = cmul(wa3, y3);
        }
        #pragma unroll
        for (int c = 0; c < 4; c++) {
            float2 y0, y1, y2, y3;
            bfly4<INV>(z[0][c], z[1][c], z[2][c], z[3][c], y0, y1, y2, y3);
            float2 o1 = cmul(wb1, y1);
            float2 o2 = cmul(wb2, y2);
            float2 o3 = cmul(wb3, y3);
            int ob = 16 * bq + m * c + k;
            int a0 = ob, a1 = ob + 4 * m, a2 = ob + 8 * m, a3 = ob + 12 * m;
            if (swW) { a0 = SWIZ(a0); a1 = SWIZ(a1); a2 = SWIZ(a2); a3 = SWIZ(a3); }
            dst[a0] = y0;
            dst[a1] = o1;
            dst[a2] = o2;
            dst[a3] = o3;
        }
        __syncthreads();
    }
}

// ---------------- K2: rfft(filter, 8192), scale folded in --------------------
extern __shared__ __align__(16) float smem_raw[];
__global__ void k_filterfft() {
    int d = blockIdx.x, tid = threadIdx.x;
    float2* tw   = (float2*)smem_raw;
    float2* bufA = tw + 1024;
    float2* bufB = bufA + NF;

    for (int j = tid; j < 1024; j += 256) tw[j] = g_tw1[j];
    const float2* kr = (const float2*)(g_kfilt + (size_t)d * LSEQ);
    for (int n = tid; n < NFH; n += 256) bufA[n] = kr[n];
    for (int n = NFH + tid; n < NF; n += 256) bufA[n] = make_float2(0.f, 0.f);
    __syncthreads();

    fft16<0>(bufA, bufB, tw, tid);   // result in bufB

    const float sc = 1.0f / (float)NF;
    for (int k = tid; k <= NFH; k += 256) {
        float2 Zk = bufB[k];
        float2 Zm = bufB[(NF - k) & (NF - 1)];
        float2 E  = make_float2(0.5f * (Zk.x + Zm.x), 0.5f * (Zk.y - Zm.y));
        float2 O  = make_float2(0.5f * (Zk.y + Zm.y), -0.5f * (Zk.x - Zm.x));
        float2 wu = g_twu[k];
        float2 W  = make_float2(wu.x, -wu.y);
        float2 WO = cmul(W, O);
        g_Kf[(size_t)d * KSTRIDE + k]        = make_float2(sc * (E.x + WO.x), sc * (E.y + WO.y));
        g_Kf[(size_t)d * KSTRIDE + (NF - k)] = make_float2(sc * (E.x - WO.x), sc * (-(E.y - WO.y)));
    }
}

// ---------------- K3: FUSED projection GEMM + halo + shortconv + gates -------
#define FP_ASTR 36
#define FP_BSTR 104
#define FP_ASZ  (128 * FP_ASTR)          // 4608 floats
#define FP_BSZ  (32 * FP_BSTR)           // 3328 floats
#define FP_SMEM ((2 * FP_ASZ + 2 * FP_BSZ) * 4)   // 63488 bytes = 15872 floats
#define FP_HALO 13520                    // float offset of u-halo rows (2 x 256)

__global__ void __launch_bounds__(256, 2) k_projfuse(const float* __restrict__ b_in,
                                                     const float* __restrict__ short_w,
                                                     const float* __restrict__ short_b) {
    extern __shared__ float sm[];
    uint32_t smb = (uint32_t)__cvta_generic_to_shared(sm);
    const int d0   = blockIdx.x * 32;        // 8 d-blocks
    const int tile = blockIdx.y;             // 0..511
    const int b  = tile >> 5;
    const int tt = tile & 31;
    const int l0 = tt * 128;
    const size_t mrow0 = (size_t)b * LSEQ + l0;

    const int tid = threadIdx.x;
    const int lane = tid & 31;
    const int warp = tid >> 5;
    const int g = lane >> 2, tg = lane & 3;
    const int wm = (warp >> 2) * 64, wn = (warp & 3) * 24;

    float4 c[4][3];
    #pragma unroll
    for (int i = 0; i < 4; i++)
        #pragma unroll
        for (int j = 0; j < 3; j++) c[i][j] = make_float4(0.f, 0.f, 0.f, 0.f);

    #pragma unroll 1
    for (int kt = 0; kt < 8; kt++) {
        if (kt == 0) {
            #pragma unroll
            for (int i = 0; i < 4; i++) {
                int ch = tid + i * 256;
                int mm = ch >> 3, kq = (ch & 7) * 4;
                CPA16(smb + (mm * FP_ASTR + kq) * 4,
                      g_ur + (mrow0 + mm) * DDIM + kq);
            }
            #pragma unroll
            for (int i = 0; i < 3; i++) {
                int ch = tid + i * 256;
                int kk = ch / 24, j = ch % 24;
                int s = j >> 3, q = j & 7;
                CPA16(smb + (2 * FP_ASZ + kk * FP_BSTR + s * 32 + q * 4) * 4,
                      g_WinT + (size_t)kk * NIN + s * 256 + d0 + q * 4);
            }
            CPA_COMMIT();
        }
        if (kt < 7) {
            int buf = (kt + 1) & 1;
            int kb = (kt + 1) * 32;
            #pragma unroll
            for (int i = 0; i < 4; i++) {
                int ch = tid + i * 256;
                int mm = ch >> 3, kq = (ch & 7) * 4;
                CPA16(smb + (buf * FP_ASZ + mm * FP_ASTR + kq) * 4,
                      g_ur + (mrow0 + mm) * DDIM + kb + kq);
            }
            #pragma unroll
            for (int i = 0; i < 3; i++) {
                int ch = tid + i * 256;
                int kk = ch / 24, j = ch % 24;
                int s = j >> 3, q = j & 7;
                CPA16(smb + (2 * FP_ASZ + buf * FP_BSZ + kk * FP_BSTR + s * 32 + q * 4) * 4,
                      g_WinT + (size_t)(kb + kk) * NIN + s * 256 + d0 + q * 4);
            }
            CPA_COMMIT();
            asm volatile("cp.async.wait_group 1;");
        } else {
            asm volatile("cp.async.wait_group 0;");
        }
        __syncthreads();

        const float* A = sm + (kt & 1) * FP_ASZ;
        const float* B = sm + 2 * FP_ASZ + (kt & 1) * FP_BSZ;
        #pragma unroll
        for (int ks = 0; ks < 4; ks++) {
            int k8 = ks * 8;
            uint32_t af[4][4], bf[3][2];
            #pragma unroll
            for (int mt = 0; mt < 4; mt++) {
                int r = (wm + mt * 16 + g) * FP_ASTR + k8 + tg;
                af[mt][0] = __float_as_uint(A[r]);                  // pre-rounded
                af[mt][1] = __float_as_uint(A[r + 8 * FP_ASTR]);
                af[mt][2] = __float_as_uint(A[r + 4]);
                af[mt][3] = __float_as_uint(A[r + 8 * FP_ASTR + 4]);
            }
            #pragma unroll
            for (int nt = 0; nt < 3; nt++) {
                int cb = (k8 + tg) * FP_BSTR + wn + nt * 8 + g;
                bf[nt][0] = __float_as_uint(B[cb]);                 // pre-rounded
                bf[nt][1] = __float_as_uint(B[cb + 4 * FP_BSTR]);
            }
            #pragma unroll
            for (int mt = 0; mt < 4; mt++)
                #pragma unroll
                for (int nt = 0; nt < 3; nt++)
                    MMA_TF32(c[mt][nt], af[mt], bf[nt]);
        }
        __syncthreads();
    }

    // ---- load u halo rows (l0-2, l0-1) into free smem ----
    #pragma unroll
    for (int i = 0; i < 2; i++) {
        int idx = tid + i * 256;          // 0..511
        int r = idx >> 8, kcol = idx & 255;
        int l = l0 - 2 + r;
        sm[FP_HALO + idx] = (l >= 0) ? g_ur[((size_t)b * LSEQ + l) * DDIM + kcol] : 0.f;
    }

    // ---- stage GEMM rows 2..129 of uc tile ----
    #pragma unroll
    for (int nt = 0; nt < 3; nt++) {
        int col = wn + nt * 8 + 2 * tg;
        int s = col >> 5, dc = col & 31;
        int e = s * 256 + d0 + dc;
        float bi0 = b_in[e], bi1 = b_in[e + 1];
        #pragma unroll
        for (int mt = 0; mt < 4; mt++) {
            int row = wm + mt * 16 + g + 2;
            sm[row * FP_BSTR + col]           = c[mt][nt].x + bi0;
            sm[row * FP_BSTR + col + 1]       = c[mt][nt].y + bi1;
            sm[(row + 8) * FP_BSTR + col]     = c[mt][nt].z + bi0;
            sm[(row + 8) * FP_BSTR + col + 1] = c[mt][nt].w + bi1;
        }
    }
    __syncthreads();

    // ---- halo rows 0..1 via dot-product against L2-resident WinT ----
    if (tid < 192) {
        int r = tid / 96, col = tid % 96;
        int s = col >> 5, dc = col & 31;
        int e = s * 256 + d0 + dc;
        int l = l0 - 2 + r;
        const float* su = sm + FP_HALO + r * 256;
        float a0 = 0.f, a1 = 0.f, a2 = 0.f, a3 = 0.f;
        #pragma unroll 2
        for (int k = 0; k < 256; k += 4) {
            a0 += su[k]     * g_WinT[k * NIN + e];
            a1 += su[k + 1] * g_WinT[(k + 1) * NIN + e];
            a2 += su[k + 2] * g_WinT[(k + 2) * NIN + e];
            a3 += su[k + 3] * g_WinT[(k + 3) * NIN + e];
        }
        float acc = (a0 + a1) + (a2 + a3);
        sm[r * FP_BSTR + col] = (l >= 0) ? acc + b_in[e] : 0.f;
    }
    __syncthreads();

    // ---- conv3 + gates, write (b,d,l) ----
    {
        int d  = tid & 31;
        int lg = tid >> 5;
        float w[3][3], sb[3];
        #pragma unroll
        for (int s = 0; s < 3; s++) {
            int e = s * 256 + d0 + d;
            w[s][0] = short_w[e * 3 + 0];
            w[s][1] = short_w[e * 3 + 1];
            w[s][2] = short_w[e * 3 + 2];
            sb[s]   = short_b[e];
        }
        float p2[3], p1[3];
        #pragma unroll
        for (int s = 0; s < 3; s++) {
            p2[s] = sm[(lg * 16 + 0) * FP_BSTR + s * 32 + d];
            p1[s] = sm[(lg * 16 + 1) * FP_BSTR + s * 32 + d];
        }
        float4 xb[4], vb[4];
        float* xf = (float*)xb;
        float* vf = (float*)vb;
        #pragma unroll
        for (int i = 0; i < 16; i++) {
            float cv[3], cur[3];
            #pragma unroll
            for (int s = 0; s < 3; s++) {
                cur[s] = sm[(lg * 16 + i + 2) * FP_BSTR + s * 32 + d];
                cv[s]  = p2[s] * w[s][0] + p1[s] * w[s][1] + cur[s] * w[s][2] + sb[s];
                p2[s] = p1[s]; p1[s] = cur[s];
            }
            xf[i] = cv[0];
            vf[i] = cv[1] * cv[2];
        }
        size_t rowo = ((size_t)b * DDIM + d0 + d) * LSEQ + l0 + lg * 16;
        float4* xo = (float4*)(g_x0t + rowo);
        float4* vo = (float4*)(g_vint + rowo);
        #pragma unroll
        for (int q = 0; q < 4; q++) { xo[q] = xb[q]; vo[q] = vb[q]; }
    }
}

// ---------------- K5: FFT long conv per (b,d) row ----------------------------
__global__ void k_fftconv(const float* __restrict__ filter_bias) {
    int row = blockIdx.x;
    int tid = threadIdx.x;
    int d   = row & (DDIM - 1);

    float2* tw   = (float2*)smem_raw;
    float2* bufA = tw + 1024;
    float2* bufB = bufA + NF;

    for (int j = tid; j < 1024; j += 256) tw[j] = g_tw1[j];
    const float2* vin2 = (const float2*)(g_vint + (size_t)row * LSEQ);
    for (int n = tid; n < NFH; n += 256) bufA[n] = vin2[n];
    for (int n = NFH + tid; n < NF; n += 256) bufA[n] = make_float2(0.f, 0.f);
    __syncthreads();

    fft16<0>(bufA, bufB, tw, tid);     // spectrum in bufB

    const float2* Kfr = g_Kf + (size_t)d * KSTRIDE;
    for (int k = tid; k <= NFH; k += 256) {
        float2 Zk = bufB[k];
        float2 Zm = bufB[(NF - k) & (NF - 1)];
        float2 E  = make_float2(0.5f * (Zk.x + Zm.x), 0.5f * (Zk.y - Zm.y));
        float2 O  = make_float2(0.5f * (Zk.y + Zm.y), -0.5f * (Zk.x - Zm.x));
        float2 wu = g_twu[k];
        float cs = wu.x, sn = wu.y;
        float2 W  = make_float2(cs, -sn);
        float2 WO = cmul(W, O);
        float2 Xk = make_float2(E.x + WO.x, E.y + WO.y);
        float2 Xm = make_float2(E.x - WO.x, -(E.y - WO.y));
        float2 Yk = cmul(Xk, Kfr[k]);
        float2 Ym = cmul(Xm, Kfr[NF - k]);
        float2 Ep = make_float2(0.5f * (Yk.x + Ym.x), 0.5f * (Yk.y - Ym.y));
        float2 Dm = make_float2(0.5f * (Yk.x - Ym.x), 0.5f * (Yk.y + Ym.y));
        float2 Wp = make_float2(cs, sn);
        float2 Op = cmul(Wp, Dm);
        float2 Zpk = make_float2(Ep.x - Op.y, Ep.y + Op.x);
        if (k == 0) {
            bufB[0] = Zpk;
        } else {
            bufB[k]      = Zpk;
            bufB[NF - k] = make_float2(Ep.x + Op.y, Op.x - Ep.y);
        }
    }
    __syncthreads();

    fft16<1>(bufB, bufA, tw, tid);     // time-domain in bufA

    float bias = filter_bias[d];
    const float2* x0r  = (const float2*)(g_x0t + (size_t)row * LSEQ);
    float2*       outr = (float2*)(g_vint + (size_t)row * LSEQ);
    for (int n = tid; n < NFH; n += 256) {
        float2 z   = bufA[n];
        float2 v   = vin2[n];
        float2 x0v = x0r[n];
        outr[n] = make_float2(tf32r((z.x + v.x * bias) * x0v.x),
                              tf32r((z.y + v.y * bias) * x0v.y));
    }
}

// ---------------- K6: output GEMM, tf32 mma.sync (operands pre-rounded) ------
#define OG_STR 136
#define OG_ASZ (32 * OG_STR)
#define OG_BSZ (32 * OG_STR)

__global__ void __launch_bounds__(256, 2) k_outgemm(float* __restrict__ out,
                                                    const float* __restrict__ b_out) {
    extern __shared__ float sm[];
    uint32_t smb = (uint32_t)__cvta_generic_to_shared(sm);
    const int m0 = blockIdx.y * 128;
    const int n0 = blockIdx.x * 128;
    const int b  = m0 >> 12;
    const int l0 = m0 & (LSEQ - 1);
    const int tid = threadIdx.x;
    const int lane = tid & 31;
    const int warp = tid >> 5;
    const int g = lane >> 2, tg = lane & 3;
    const int wm = (warp >> 2) * 64, wn = (warp & 3) * 32;

    float4 c[4][4];
    #pragma unroll
    for (int i = 0; i < 4; i++)
        #pragma unroll
        for (int j = 0; j < 4; j++) c[i][j] = make_float4(0.f, 0.f, 0.f, 0.f);

    #pragma unroll 1
    for (int kt = 0; kt < 8; kt++) {
        if (kt == 0) {
            #pragma unroll
            for (int i = 0; i < 4; i++) {
                int ch = tid + i * 256;
                int kk = ch >> 5, mq = (ch & 31) * 4;
                CPA16(smb + (kk * OG_STR + mq) * 4,
                      g_vint + ((size_t)b * DDIM + kk) * LSEQ + l0 + mq);
                CPA16(smb + (2 * OG_ASZ + kk * OG_STR + mq) * 4,
                      g_WoutT + (size_t)kk * DDIM + n0 + mq);
            }
            CPA_COMMIT();
        }
        if (kt < 7) {
            int buf = (kt + 1) & 1;
            int kb = (kt + 1) * 32;
            #pragma unroll
            for (int i = 0; i < 4; i++) {
                int ch = tid + i * 256;
                int kk = ch >> 5, mq = (ch & 31) * 4;
                CPA16(smb + (buf * OG_ASZ + kk * OG_STR + mq) * 4,
                      g_vint + ((size_t)b * DDIM + kb + kk) * LSEQ + l0 + mq);
                CPA16(smb + (2 * OG_ASZ + buf * OG_BSZ + kk * OG_STR + mq) * 4,
                      g_WoutT + (size_t)(kb + kk) * DDIM + n0 + mq);
            }
            CPA_COMMIT();
            asm volatile("cp.async.wait_group 1;");
        } else {
            asm volatile("cp.async.wait_group 0;");
        }
        __syncthreads();

        const float* A = sm + (kt & 1) * OG_ASZ;
        const float* B = sm + 2 * OG_ASZ + (kt & 1) * OG_BSZ;
        #pragma unroll
        for (int ks = 0; ks < 4; ks++) {
            int k8 = ks * 8;
            uint32_t af[4][4], bf[4][2];
            #pragma unroll
            for (int mt = 0; mt < 4; mt++) {
                int mrow = wm + mt * 16 + g;
                int r = (k8 + tg) * OG_STR + mrow;
                af[mt][0] = __float_as_uint(A[r]);
                af[mt][1] = __float_as_uint(A[r + 8]);
                af[mt][2] = __float_as_uint(A[r + 4 * OG_STR]);
                af[mt][3] = __float_as_uint(A[r + 4 * OG_STR + 8]);
            }
            #pragma unroll
            for (int nt = 0; nt < 4; nt++) {
                int cb = (k8 + tg) * OG_STR + wn + nt * 8 + g;
                bf[nt][0] = __float_as_uint(B[cb]);
                bf[nt][1] = __float_as_uint(B[cb + 4 * OG_STR]);
            }
            #pragma unroll
            for (int mt = 0; mt < 4; mt++)
                #pragma unroll
                for (int nt = 0; nt < 4; nt++)
                    MMA_TF32(c[mt][nt], af[mt], bf[nt]);
        }
        __syncthreads();
    }

    #pragma unroll
    for (int nt = 0; nt < 4; nt++) {
        int col = n0 + wn + nt * 8 + tg * 2;
        float2 bi = *(const float2*)(b_out + col);
        #pragma unroll
        for (int mt = 0; mt < 4; mt++) {
            int row = m0 + wm + mt * 16 + g;
            float2 v0 = make_float2(c[mt][nt].x + bi.x, c[mt][nt].y + bi.y);
            float2 v1 = make_float2(c[mt][nt].z + bi.x, c[mt][nt].w + bi.y);
            *(float2*)(out + (size_t)row * DDIM + col)       = v0;
            *(float2*)(out + (size_t)(row + 8) * DDIM + col) = v1;
        }
    }
}

// ---------------- launch ------------------------------------------------------
extern "C" void kernel_launch(void* const* d_in, const int* in_sizes, int n_in,
                              void* d_out, int out_size) {
    const float* u       = (const float*)d_in[0];
    const float* W_in    = (const float*)d_in[1];
    const float* b_in    = (const float*)d_in[2];
    const float* short_w = (const float*)d_in[3];
    const float* short_b = (const float*)d_in[4];
    const float* mlp_w1  = (const float*)d_in[5];
    const float* mlp_b1  = (const float*)d_in[6];
    const float* freq    = (const float*)d_in[7];
    const float* mlp_w2  = (const float*)d_in[8];
    const float* mlp_b2  = (const float*)d_in[9];
    const float* mlp_w3  = (const float*)d_in[10];
    const float* mlp_b3  = (const float*)d_in[11];
    const float* mlp_w4  = (const float*)d_in[12];
    const float* fbias   = (const float*)d_in[13];
    const float* W_out   = (const float*)d_in[14];
    const float* b_out   = (const float*)d_in[15];
    float* out = (float*)d_out;

    (void)in_sizes; (void)n_in; (void)out_size;

    const int smemFFT = 1024 * 8 + NF * 8 * 2;
    const int smemOG  = (2 * OG_ASZ + 2 * OG_BSZ) * 4;
    cudaFuncSetAttribute(k_filterfft, cudaFuncAttributeMaxDynamicSharedMemorySize, smemFFT);
    cudaFuncSetAttribute(k_fftconv,   cudaFuncAttributeMaxDynamicSharedMemorySize, smemFFT);
    cudaFuncSetAttribute(k_projfuse,  cudaFuncAttributeMaxDynamicSharedMemorySize, FP_SMEM);
    cudaFuncSetAttribute(k_outgemm,   cudaFuncAttributeMaxDynamicSharedMemorySize, smemOG);

    k_transpose<<<(DDIM * NIN + DDIM * DDIM + 255) / 256, 256>>>(W_in, W_out);
    k_roundu<<<16384, 256>>>((const float4*)u);
    k_filter<<<LSEQ / 4, 256>>>(mlp_w1, mlp_b1, freq, mlp_w2, mlp_b2, mlp_w3, mlp_b3, mlp_w4);
    k_filterfft<<<DDIM, 256, smemFFT>>>();
    k_projfuse<<<dim3(DDIM / 32, BB * 32), 256, FP_SMEM>>>(b_in, short_w, short_b);
    k_fftconv<<<BB * DDIM, 256, smemFFT>>>(fbias);
    k_outgemm<<<dim3(DDIM / 128, (BB * LSEQ) / 128), 256, smemOG>>>(out, b_out);
}

// round 12
// speedup vs baseline: 1.0884x; 1.0884x over previous
#include <cuda_runtime.h>
#include <math.h>
#include <stdint.h>

#define BB    16
#define LSEQ  4096
#define DDIM  256
#define NIN   768
#define NF    4096
#define NFH   2048
#define KSTRIDE 4104
#define PI_F  3.14159265358979323846f

// ---------------- scratch ----------------------------------------------------
__device__ float  g_WinT [DDIM * NIN];                 // tf32-rounded
__device__ float  g_WoutT[DDIM * DDIM];                // tf32-rounded
__device__ float  g_kfilt[DDIM * LSEQ];
__device__ float2 g_Kf   [DDIM * KSTRIDE];
__device__ float  g_halo [(size_t)BB * 32 * 2 * NIN];  // x at tile-boundary rows
__device__ float  g_x0t  [(size_t)BB * DDIM * LSEQ];
__device__ float  g_vint [(size_t)BB * DDIM * LSEQ];
__device__ float2 g_tw1  [1024];
__device__ float2 g_twu  [2049];

__device__ __forceinline__ float2 cmul(float2 a, float2 b) {
    return make_float2(a.x * b.x - a.y * b.y, a.x * b.y + a.y * b.x);
}

#define CPA16(dst_u32, src_ptr) \
    asm volatile("cp.async.cg.shared.global [%0], [%1], 16;" :: "r"(dst_u32), "l"(src_ptr))
#define CPA_COMMIT() asm volatile("cp.async.commit_group;")

#define MMA_TF32(C, A, B) \
    asm volatile("mma.sync.aligned.m16n8k8.row.col.f32.tf32.tf32.f32 " \
        "{%0,%1,%2,%3}, {%4,%5,%6,%7}, {%8,%9}, {%0,%1,%2,%3};" \
        : "+f"(C.x), "+f"(C.y), "+f"(C.z), "+f"(C.w) \
        : "r"(A[0]), "r"(A[1]), "r"(A[2]), "r"(A[3]), "r"(B[0]), "r"(B[1]))

__device__ __forceinline__ uint32_t f2tf32(float v) {
    uint32_t r;
    asm("cvt.rna.tf32.f32 %0, %1;" : "=r"(r) : "f"(v));
    return r;
}
__device__ __forceinline__ float tf32r(float v) { return __uint_as_float(f2tf32(v)); }

// ---------------- K0: transpose + tf32-round weights + twiddles --------------
__global__ void k_transpose(const float* __restrict__ Win, const float* __restrict__ Wout) {
    int i = blockIdx.x * blockDim.x + threadIdx.x;
    if (i < DDIM * NIN) {
        int d = i / NIN, e = i % NIN;
        g_WinT[i] = tf32r(Win[e * DDIM + d]);
    }
    int j = i - DDIM * NIN;
    if (j >= 0 && j < DDIM * DDIM) {
        int d = j / DDIM, n = j % DDIM;
        g_WoutT[j] = tf32r(Wout[n * DDIM + d]);
    }
    if (i < 1024) {
        float ang = -2.0f * PI_F * (float)i / (float)NF;
        float sn, cs; sincosf(ang, &sn, &cs);
        g_tw1[i] = make_float2(cs, sn);
    }
    if (i < 2049) {
        float ang = PI_F * (float)i / (float)NF;
        float sn, cs; sincosf(ang, &sn, &cs);
        g_twu[i] = make_float2(cs, sn);
    }
}

// ---------------- K1: implicit filter MLP (4 l per block) --------------------
__global__ void k_filter(const float* __restrict__ w1, const float* __restrict__ b1,
                         const float* __restrict__ fr,
                         const float* __restrict__ w2, const float* __restrict__ b2,
                         const float* __restrict__ w3, const float* __restrict__ b3,
                         const float* __restrict__ w4) {
    int lq = threadIdx.x >> 6;
    int j  = threadIdx.x & 63;
    int l  = blockIdx.x * 4 + lq;
    __shared__ float hA[4][64], hB[4][64];

    float t    = (float)l * (1.0f / (float)(LSEQ - 1));
    float wang = 2.0f * PI_F * (float)l / (float)LSEQ;
    const float f0 = 1e-4f;
    float z0 = t, z1 = cosf(f0 * wang), z2 = -sinf(f0 * wang);

    float a = z0 * w1[j * 3 + 0] + z1 * w1[j * 3 + 1] + z2 * w1[j * 3 + 2] + b1[j];
    hA[lq][j] = sinf(fr[j] * a);
    __syncthreads();

    float s = b2[j];
    #pragma unroll
    for (int i = 0; i < 64; i++) s += hA[lq][i] * w2[j * 64 + i];
    hB[lq][j] = sinf(fr[j] * s);
    __syncthreads();

    s = b3[j];
    #pragma unroll
    for (int i = 0; i < 64; i++) s += hB[lq][i] * w3[j * 64 + i];
    float hv = sinf(fr[j] * s);
    __syncthreads();
    hA[lq][j] = hv;
    __syncthreads();

    const float min_d = logf(0.01f) / 1.5f;
    const float max_d = logf(0.01f) / 0.3f;
    #pragma unroll
    for (int r = 0; r < 4; r++) {
        int d = j * 4 + r;
        float s4 = 0.f;
        #pragma unroll
        for (int i = 0; i < 64; i++) s4 += hA[lq][i] * w4[d * 64 + i];
        float delta = fabsf(min_d + (max_d - min_d) * ((float)d / (float)(DDIM - 1)));
        g_kfilt[d * LSEQ + l] = s4 * expf(-t * delta);
    }
}

// ---------------- K1b: boundary-row projections (halo), ILP-unrolled ---------
__global__ void k_halo(const float* __restrict__ u) {
    __shared__ float su[8][256];
    int tid = threadIdx.x;                 // 256
    int rg  = blockIdx.x;                  // 0..7
    int b   = blockIdx.y;                  // 0..15
    int e   = blockIdx.z * 256 + tid;      // 0..767

    #pragma unroll
    for (int j = 0; j < 8; j++) {
        int r = rg * 8 + j;
        int t = r >> 1, w_ = r & 1;
        int l = t * 128 - 2 + w_;
        su[j][tid] = (l >= 0) ? u[((size_t)b * LSEQ + l) * DDIM + tid] : 0.f;
    }
    __syncthreads();

    float acc[8] = {};
    #pragma unroll 2
    for (int k = 0; k < 256; k += 4) {
        float wv0 = g_WinT[(k + 0) * NIN + e];
        float wv1 = g_WinT[(k + 1) * NIN + e];
        float wv2 = g_WinT[(k + 2) * NIN + e];
        float wv3 = g_WinT[(k + 3) * NIN + e];
        #pragma unroll
        for (int j = 0; j < 8; j++) {
            acc[j] += su[j][k] * wv0 + su[j][k + 1] * wv1
                    + su[j][k + 2] * wv2 + su[j][k + 3] * wv3;
        }
    }
    #pragma unroll
    for (int j = 0; j < 8; j++) {
        int r = rg * 8 + j;
        int t = r >> 1, w_ = r & 1;
        g_halo[(((size_t)b * 32 + t) * 2 + w_) * NIN + e] = acc[j];
    }
}

// ---------------- radix-16 Stockham FFT: twiddles from L2 --------------------
#define SWIZ(a) ((a) ^ (((a) >> 4) & 15))

template<int INV>
__device__ __forceinline__ void bfly4(float2 s0, float2 s1, float2 s2, float2 s3,
                                      float2& y0, float2& y1, float2& y2, float2& y3) {
    float u0x = s0.x + s2.x, u0y = s0.y + s2.y;
    float u1x = s0.x - s2.x, u1y = s0.y - s2.y;
    float u2x = s1.x + s3.x, u2y = s1.y + s3.y;
    float u3x = s1.x - s3.x, u3y = s1.y - s3.y;
    y0 = make_float2(u0x + u2x, u0y + u2y);
    y2 = make_float2(u0x - u2x, u0y - u2y);
    if (INV) {
        y1 = make_float2(u1x - u3y, u1y + u3x);
        y3 = make_float2(u1x + u3y, u1y - u3x);
    } else {
        y1 = make_float2(u1x + u3y, u1y - u3x);
        y3 = make_float2(u1x - u3y, u1y + u3x);
    }
}

template<int INV>
__device__ __forceinline__ void fft16(float2* __restrict__ buf0, float2* __restrict__ buf1,
                                      int tid) {
    const float C8 = 0.9238795325112867f;
    const float S8 = 0.3826834323650898f;
    const float C4 = 0.7071067811865476f;
    const float sg = INV ? 1.0f : -1.0f;
    const float2 F1 = make_float2( C8, sg * S8);
    const float2 F2 = make_float2( C4, sg * C4);
    const float2 F3 = make_float2( S8, sg * C8);
    const float2 F4 = make_float2(0.f, sg * 1.f);
    const float2 F6 = make_float2(-C4, sg * C4);
    const float2 F9 = make_float2(-C8, -sg * S8);

    #pragma unroll
    for (int s = 0; s < 3; s++) {
        const int m = (s == 0) ? 1 : (s == 1) ? 16 : 256;
        const float2* src = (s == 1) ? buf1 : buf0;
        float2*       dst = (s == 1) ? buf0 : buf1;
        const bool swR = (s == 1), swW = (s == 0);

        int k  = tid & (m - 1);
        int bq = tid - k;

        float2 wa1 = __ldg(&g_tw1[bq]);      // L2-resident twiddle table
        if (INV) wa1.y = -wa1.y;

        float2 X[4][4];
        #pragma unroll
        for (int j = 0; j < 4; j++)
            #pragma unroll
            for (int r = 0; r < 4; r++) {
                int a = tid + 256 * r + 1024 * j;
                X[r][j] = src[swR ? SWIZ(a) : a];
            }

        float2 wa2 = cmul(wa1, wa1);
        float2 wa3 = cmul(wa2, wa1);
        float2 wb1 = cmul(wa2, wa2);
        float2 wb2 = cmul(wb1, wb1);
        float2 wb3 = cmul(wb2, wb1);

        float2 z[4][4];
        #pragma unroll
        for (int r = 0; r < 4; r++) {
            float2 y0, y1, y2, y3;
            bfly4<INV>(X[r][0], X[r][1], X[r][2], X[r][3], y0, y1, y2, y3);
            if (r == 1) { y1 = cmul(F1, y1); y2 = cmul(F2, y2); y3 = cmul(F3, y3); }
            if (r == 2) { y1 = cmul(F2, y1); y2 = cmul(F4, y2); y3 = cmul(F6, y3); }
            if (r == 3) { y1 = cmul(F3, y1); y2 = cmul(F6, y2); y3 = cmul(F9, y3); }
            z[r][0] = y0;
            z[r][1] = cmul(wa1, y1);
            z[r][2] = cmul(wa2, y2);
            z[r][3] = cmul(wa3, y3);
        }
        #pragma unroll
        for (int c = 0; c < 4; c++) {
            float2 y0, y1, y2, y3;
            bfly4<INV>(z[0][c], z[1][c], z[2][c], z[3][c], y0, y1, y2, y3);
            float2 o1 = cmul(wb1, y1);
            float2 o2 = cmul(wb2, y2);
            float2 o3 = cmul(wb3, y3);
            int ob = 16 * bq + m * c + k;
            int a0 = ob, a1 = ob + 4 * m, a2 = ob + 8 * m, a3 = ob + 12 * m;
            if (swW) { a0 = SWIZ(a0); a1 = SWIZ(a1); a2 = SWIZ(a2); a3 = SWIZ(a3); }
            dst[a0] = y0;
            dst[a1] = o1;
            dst[a2] = o2;
            dst[a3] = o3;
        }
        __syncthreads();
    }
}

// ---------------- K2: rfft(filter, 8192), scale folded in --------------------
extern __shared__ __align__(16) float smem_raw[];
__global__ void k_filterfft() {
    int d = blockIdx.x, tid = threadIdx.x;
    float2* bufA = (float2*)smem_raw;
    float2* bufB = bufA + NF;

    const float2* kr = (const float2*)(g_kfilt + (size_t)d * LSEQ);
    for (int n = tid; n < NFH; n += 256) bufA[n] = kr[n];
    for (int n = NFH + tid; n < NF; n += 256) bufA[n] = make_float2(0.f, 0.f);
    __syncthreads();

    fft16<0>(bufA, bufB, tid);   // result in bufB

    const float sc = 1.0f / (float)NF;
    for (int k = tid; k <= NFH; k += 256) {
        float2 Zk = bufB[k];
        float2 Zm = bufB[(NF - k) & (NF - 1)];
        float2 E  = make_float2(0.5f * (Zk.x + Zm.x), 0.5f * (Zk.y - Zm.y));
        float2 O  = make_float2(0.5f * (Zk.y + Zm.y), -0.5f * (Zk.x - Zm.x));
        float2 wu = g_twu[k];
        float2 W  = make_float2(wu.x, -wu.y);
        float2 WO = cmul(W, O);
        g_Kf[(size_t)d * KSTRIDE + k]        = make_float2(sc * (E.x + WO.x), sc * (E.y + WO.y));
        g_Kf[(size_t)d * KSTRIDE + (NF - k)] = make_float2(sc * (E.x - WO.x), sc * (-(E.y - WO.y)));
    }
}

// ---------------- K3: FUSED projection GEMM + shortconv + gates --------------
#define FP_ASTR 36
#define FP_BSTR 104
#define FP_ASZ  (128 * FP_ASTR)
#define FP_BSZ  (32 * FP_BSTR)
#define FP_SMEM ((2 * FP_ASZ + 2 * FP_BSZ) * 4)   // 63488 bytes

__global__ void __launch_bounds__(256, 2) k_projfuse(const float* __restrict__ u,
                                                     const float* __restrict__ b_in,
                                                     const float* __restrict__ short_w,
                                                     const float* __restrict__ short_b) {
    extern __shared__ float sm[];
    uint32_t smb = (uint32_t)__cvta_generic_to_shared(sm);
    const int d0   = blockIdx.x * 32;        // 8 d-blocks
    const int tile = blockIdx.y;             // 0..511
    const int b  = tile >> 5;
    const int tt = tile & 31;
    const int l0 = tt * 128;
    const size_t mrow0 = (size_t)b * LSEQ + l0;

    const int tid = threadIdx.x;
    const int lane = tid & 31;
    const int warp = tid >> 5;
    const int g = lane >> 2, tg = lane & 3;
    const int wm = (warp >> 2) * 64, wn = (warp & 3) * 24;

    float4 c[4][3];
    #pragma unroll
    for (int i = 0; i < 4; i++)
        #pragma unroll
        for (int j = 0; j < 3; j++) c[i][j] = make_float4(0.f, 0.f, 0.f, 0.f);

    #pragma unroll 1
    for (int kt = 0; kt < 8; kt++) {
        if (kt == 0) {
            #pragma unroll
            for (int i = 0; i < 4; i++) {
                int ch = tid + i * 256;
                int mm = ch >> 3, kq = (ch & 7) * 4;
                CPA16(smb + (mm * FP_ASTR + kq) * 4,
                      u + (mrow0 + mm) * DDIM + kq);
            }
            #pragma unroll
            for (int i = 0; i < 3; i++) {
                int ch = tid + i * 256;
                int kk = ch / 24, j = ch % 24;
                int s = j >> 3, q = j & 7;
                CPA16(smb + (2 * FP_ASZ + kk * FP_BSTR + s * 32 + q * 4) * 4,
                      g_WinT + (size_t)kk * NIN + s * 256 + d0 + q * 4);
            }
            CPA_COMMIT();
        }
        if (kt < 7) {
            int buf = (kt + 1) & 1;
            int kb = (kt + 1) * 32;
            #pragma unroll
            for (int i = 0; i < 4; i++) {
                int ch = tid + i * 256;
                int mm = ch >> 3, kq = (ch & 7) * 4;
                CPA16(smb + (buf * FP_ASZ + mm * FP_ASTR + kq) * 4,
                      u + (mrow0 + mm) * DDIM + kb + kq);
            }
            #pragma unroll
            for (int i = 0; i < 3; i++) {
                int ch = tid + i * 256;
                int kk = ch / 24, j = ch % 24;
                int s = j >> 3, q = j & 7;
                CPA16(smb + (2 * FP_ASZ + buf * FP_BSZ + kk * FP_BSTR + s * 32 + q * 4) * 4,
                      g_WinT + (size_t)(kb + kk) * NIN + s * 256 + d0 + q * 4);
            }
            CPA_COMMIT();
            asm volatile("cp.async.wait_group 1;");
        } else {
            asm volatile("cp.async.wait_group 0;");
        }
        __syncthreads();

        const float* A = sm + (kt & 1) * FP_ASZ;
        const float* B = sm + 2 * FP_ASZ + (kt & 1) * FP_BSZ;
        #pragma unroll
        for (int ks = 0; ks < 4; ks++) {
            int k8 = ks * 8;
            uint32_t af[4][4], bf[3][2];
            #pragma unroll
            for (int mt = 0; mt < 4; mt++) {
                int r = (wm + mt * 16 + g) * FP_ASTR + k8 + tg;
                af[mt][0] = f2tf32(A[r]);
                af[mt][1] = f2tf32(A[r + 8 * FP_ASTR]);
                af[mt][2] = f2tf32(A[r + 4]);
                af[mt][3] = f2tf32(A[r + 8 * FP_ASTR + 4]);
            }
            #pragma unroll
            for (int nt = 0; nt < 3; nt++) {
                int cb = (k8 + tg) * FP_BSTR + wn + nt * 8 + g;
                bf[nt][0] = __float_as_uint(B[cb]);                 // pre-rounded
                bf[nt][1] = __float_as_uint(B[cb + 4 * FP_BSTR]);
            }
            #pragma unroll
            for (int mt = 0; mt < 4; mt++)
                #pragma unroll
                for (int nt = 0; nt < 3; nt++)
                    MMA_TF32(c[mt][nt], af[mt], bf[nt]);
        }
        __syncthreads();
    }

    // ---- stage uc tile: rows 0..1 = halo (zero for l<0), rows 2..129 = GEMM --
    if (tid < 192) {
        int r = tid / 96, col = tid % 96;
        int s = col >> 5, dc = col & 31;
        int e = s * 256 + d0 + dc;
        int l = l0 - 2 + r;
        float hv = g_halo[(((size_t)b * 32 + tt) * 2 + r) * NIN + e];
        sm[r * FP_BSTR + col] = (l >= 0) ? hv + b_in[e] : 0.f;
    }
    #pragma unroll
    for (int nt = 0; nt < 3; nt++) {
        int col = wn + nt * 8 + 2 * tg;
        int s = col >> 5, dc = col & 31;
        int e = s * 256 + d0 + dc;
        float bi0 = b_in[e], bi1 = b_in[e + 1];
        #pragma unroll
        for (int mt = 0; mt < 4; mt++) {
            int row = wm + mt * 16 + g + 2;
            sm[row * FP_BSTR + col]           = c[mt][nt].x + bi0;
            sm[row * FP_BSTR + col + 1]       = c[mt][nt].y + bi1;
            sm[(row + 8) * FP_BSTR + col]     = c[mt][nt].z + bi0;
            sm[(row + 8) * FP_BSTR + col + 1] = c[mt][nt].w + bi1;
        }
    }
    __syncthreads();

    // ---- conv3 + gates, write (b,d,l) ----
    {
        int d  = tid & 31;
        int lg = tid >> 5;
        float w[3][3], sb[3];
        #pragma unroll
        for (int s = 0; s < 3; s++) {
            int e = s * 256 + d0 + d;
            w[s][0] = short_w[e * 3 + 0];
            w[s][1] = short_w[e * 3 + 1];
            w[s][2] = short_w[e * 3 + 2];
            sb[s]   = short_b[e];
        }
        float p2[3], p1[3];
        #pragma unroll
        for (int s = 0; s < 3; s++) {
            p2[s] = sm[(lg * 16 + 0) * FP_BSTR + s * 32 + d];
            p1[s] = sm[(lg * 16 + 1) * FP_BSTR + s * 32 + d];
        }
        float4 xb[4], vb[4];
        float* xf = (float*)xb;
        float* vf = (float*)vb;
        #pragma unroll
        for (int i = 0; i < 16; i++) {
            float cv[3], cur[3];
            #pragma unroll
            for (int s = 0; s < 3; s++) {
                cur[s] = sm[(lg * 16 + i + 2) * FP_BSTR + s * 32 + d];
                cv[s]  = p2[s] * w[s][0] + p1[s] * w[s][1] + cur[s] * w[s][2] + sb[s];
                p2[s] = p1[s]; p1[s] = cur[s];
            }
            xf[i] = cv[0];
            vf[i] = cv[1] * cv[2];
        }
        size_t rowo = ((size_t)b * DDIM + d0 + d) * LSEQ + l0 + lg * 16;
        float4* xo = (float4*)(g_x0t + rowo);
        float4* vo = (float4*)(g_vint + rowo);
        #pragma unroll
        for (int q = 0; q < 4; q++) { xo[q] = xb[q]; vo[q] = vb[q]; }
    }
}

// ---------------- K5: FFT long conv per (b,d) row (64 KB smem -> occ 3) ------
__global__ void k_fftconv(const float* __restrict__ filter_bias) {
    int row = blockIdx.x;
    int tid = threadIdx.x;
    int d   = row & (DDIM - 1);

    float2* bufA = (float2*)smem_raw;
    float2* bufB = bufA + NF;

    const float2* vin2 = (const float2*)(g_vint + (size_t)row * LSEQ);
    for (int n = tid; n < NFH; n += 256) bufA[n] = vin2[n];
    for (int n = NFH + tid; n < NF; n += 256) bufA[n] = make_float2(0.f, 0.f);
    __syncthreads();

    fft16<0>(bufA, bufB, tid);     // spectrum in bufB

    const float2* Kfr = g_Kf + (size_t)d * KSTRIDE;
    for (int k = tid; k <= NFH; k += 256) {
        float2 Zk = bufB[k];
        float2 Zm = bufB[(NF - k) & (NF - 1)];
        float2 E  = make_float2(0.5f * (Zk.x + Zm.x), 0.5f * (Zk.y - Zm.y));
        float2 O  = make_float2(0.5f * (Zk.y + Zm.y), -0.5f * (Zk.x - Zm.x));
        float2 wu = g_twu[k];
        float cs = wu.x, sn = wu.y;
        float2 W  = make_float2(cs, -sn);
        float2 WO = cmul(W, O);
        float2 Xk = make_float2(E.x + WO.x, E.y + WO.y);
        float2 Xm = make_float2(E.x - WO.x, -(E.y - WO.y));
        float2 Yk = cmul(Xk, Kfr[k]);
        float2 Ym = cmul(Xm, Kfr[NF - k]);
        float2 Ep = make_float2(0.5f * (Yk.x + Ym.x), 0.5f * (Yk.y - Ym.y));
        float2 Dm = make_float2(0.5f * (Yk.x - Ym.x), 0.5f * (Yk.y + Ym.y));
        float2 Wp = make_float2(cs, sn);
        float2 Op = cmul(Wp, Dm);
        float2 Zpk = make_float2(Ep.x - Op.y, Ep.y + Op.x);
        if (k == 0) {
            bufB[0] = Zpk;
        } else {
            bufB[k]      = Zpk;
            bufB[NF - k] = make_float2(Ep.x + Op.y, Op.x - Ep.y);
        }
    }
    __syncthreads();

    fft16<1>(bufB, bufA, tid);     // time-domain in bufA

    float bias = filter_bias[d];
    const float2* x0r  = (const float2*)(g_x0t + (size_t)row * LSEQ);
    float2*       outr = (float2*)(g_vint + (size_t)row * LSEQ);
    for (int n = tid; n < NFH; n += 256) {
        float2 z   = bufA[n];
        float2 v   = vin2[n];
        float2 x0v = x0r[n];
        outr[n] = make_float2(tf32r((z.x + v.x * bias) * x0v.x),
                              tf32r((z.y + v.y * bias) * x0v.y));
    }
}

// ---------------- K6: output GEMM, tf32 mma.sync (operands pre-rounded) ------
#define OG_STR 136
#define OG_ASZ (32 * OG_STR)
#define OG_BSZ (32 * OG_STR)

__global__ void __launch_bounds__(256, 2) k_outgemm(float* __restrict__ out,
                                                    const float* __restrict__ b_out) {
    extern __shared__ float sm[];
    uint32_t smb = (uint32_t)__cvta_generic_to_shared(sm);
    const int m0 = blockIdx.y * 128;
    const int n0 = blockIdx.x * 128;
    const int b  = m0 >> 12;
    const int l0 = m0 & (LSEQ - 1);
    const int tid = threadIdx.x;
    const int lane = tid & 31;
    const int warp = tid >> 5;
    const int g = lane >> 2, tg = lane & 3;
    const int wm = (warp >> 2) * 64, wn = (warp & 3) * 32;

    float4 c[4][4];
    #pragma unroll
    for (int i = 0; i < 4; i++)
        #pragma unroll
        for (int j = 0; j < 4; j++) c[i][j] = make_float4(0.f, 0.f, 0.f, 0.f);

    #pragma unroll 1
    for (int kt = 0; kt < 8; kt++) {
        if (kt == 0) {
            #pragma unroll
            for (int i = 0; i < 4; i++) {
                int ch = tid + i * 256;
                int kk = ch >> 5, mq = (ch & 31) * 4;
                CPA16(smb + (kk * OG_STR + mq) * 4,
                      g_vint + ((size_t)b * DDIM + kk) * LSEQ + l0 + mq);
                CPA16(smb + (2 * OG_ASZ + kk * OG_STR + mq) * 4,
                      g_WoutT + (size_t)kk * DDIM + n0 + mq);
            }
            CPA_COMMIT();
        }
        if (kt < 7) {
            int buf = (kt + 1) & 1;
            int kb = (kt + 1) * 32;
            #pragma unroll
            for (int i = 0; i < 4; i++) {
                int ch = tid + i * 256;
                int kk = ch >> 5, mq = (ch & 31) * 4;
                CPA16(smb + (buf * OG_ASZ + kk * OG_STR + mq) * 4,
                      g_vint + ((size_t)b * DDIM + kb + kk) * LSEQ + l0 + mq);
                CPA16(smb + (2 * OG_ASZ + buf * OG_BSZ + kk * OG_STR + mq) * 4,
                      g_WoutT + (size_t)(kb + kk) * DDIM + n0 + mq);
            }
            CPA_COMMIT();
            asm volatile("cp.async.wait_group 1;");
        } else {
            asm volatile("cp.async.wait_group 0;");
        }
        __syncthreads();

        const float* A = sm + (kt & 1) * OG_ASZ;
        const float* B = sm + 2 * OG_ASZ + (kt & 1) * OG_BSZ;
        #pragma unroll
        for (int ks = 0; ks < 4; ks++) {
            int k8 = ks * 8;
            uint32_t af[4][4], bf[4][2];
            #pragma unroll
            for (int mt = 0; mt < 4; mt++) {
                int mrow = wm + mt * 16 + g;
                int r = (k8 + tg) * OG_STR + mrow;
                af[mt][0] = __float_as_uint(A[r]);
                af[mt][1] = __float_as_uint(A[r + 8]);
                af[mt][2] = __float_as_uint(A[r + 4 * OG_STR]);
                af[mt][3] = __float_as_uint(A[r + 4 * OG_STR + 8]);
            }
            #pragma unroll
            for (int nt = 0; nt < 4; nt++) {
                int cb = (k8 + tg) * OG_STR + wn + nt * 8 + g;
                bf[nt][0] = __float_as_uint(B[cb]);
                bf[nt][1] = __float_as_uint(B[cb + 4 * OG_STR]);
            }
            #pragma unroll
            for (int mt = 0; mt < 4; mt++)
                #pragma unroll
                for (int nt = 0; nt < 4; nt++)
                    MMA_TF32(c[mt][nt], af[mt], bf[nt]);
        }
        __syncthreads();
    }

    #pragma unroll
    for (int nt = 0; nt < 4; nt++) {
        int col = n0 + wn + nt * 8 + tg * 2;
        float2 bi = *(const float2*)(b_out + col);
        #pragma unroll
        for (int mt = 0; mt < 4; mt++) {
            int row = m0 + wm + mt * 16 + g;
            float2 v0 = make_float2(c[mt][nt].x + bi.x, c[mt][nt].y + bi.y);
            float2 v1 = make_float2(c[mt][nt].z + bi.x, c[mt][nt].w + bi.y);
            *(float2*)(out + (size_t)row * DDIM + col)       = v0;
            *(float2*)(out + (size_t)(row + 8) * DDIM + col) = v1;
        }
    }
}

// ---------------- launch ------------------------------------------------------
extern "C" void kernel_launch(void* const* d_in, const int* in_sizes, int n_in,
                              void* d_out, int out_size) {
    const float* u       = (const float*)d_in[0];
    const float* W_in    = (const float*)d_in[1];
    const float* b_in    = (const float*)d_in[2];
    const float* short_w = (const float*)d_in[3];
    const float* short_b = (const float*)d_in[4];
    const float* mlp_w1  = (const float*)d_in[5];
    const float* mlp_b1  = (const float*)d_in[6];
    const float* freq    = (const float*)d_in[7];
    const float* mlp_w2  = (const float*)d_in[8];
    const float* mlp_b2  = (const float*)d_in[9];
    const float* mlp_w3  = (const float*)d_in[10];
    const float* mlp_b3  = (const float*)d_in[11];
    const float* mlp_w4  = (const float*)d_in[12];
    const float* fbias   = (const float*)d_in[13];
    const float* W_out   = (const float*)d_in[14];
    const float* b_out   = (const float*)d_in[15];
    float* out = (float*)d_out;

    (void)in_sizes; (void)n_in; (void)out_size;

    const int smemFFT = NF * 8 * 2;                               // 65536
    const int smemOG  = (2 * OG_ASZ + 2 * OG_BSZ) * 4;
    cudaFuncSetAttribute(k_filterfft, cudaFuncAttributeMaxDynamicSharedMemorySize, smemFFT);
    cudaFuncSetAttribute(k_fftconv,   cudaFuncAttributeMaxDynamicSharedMemorySize, smemFFT);
    cudaFuncSetAttribute(k_projfuse,  cudaFuncAttributeMaxDynamicSharedMemorySize, FP_SMEM);
    cudaFuncSetAttribute(k_outgemm,   cudaFuncAttributeMaxDynamicSharedMemorySize, smemOG);

    k_transpose<<<(DDIM * NIN + DDIM * DDIM + 255) / 256, 256>>>(W_in, W_out);
    k_filter<<<LSEQ / 4, 256>>>(mlp_w1, mlp_b1, freq, mlp_w2, mlp_b2, mlp_w3, mlp_b3, mlp_w4);
    k_filterfft<<<DDIM, 256, smemFFT>>>();
    k_halo<<<dim3(8, BB, 3), 256>>>(u);
    k_projfuse<<<dim3(DDIM / 32, BB * 32), 256, FP_SMEM>>>(u, b_in, short_w, short_b);
    k_fftconv<<<BB * DDIM, 256, smemFFT>>>(fbias);
    k_outgemm<<<dim3(DDIM / 128, (BB * LSEQ) / 128), 256, smemOG>>>(out, b_out);
}

// round 15
// speedup vs baseline: 1.0898x; 1.0014x over previous
#include <cuda_runtime.h>
#include <math.h>
#include <stdint.h>

#define BB    16
#define LSEQ  4096
#define DDIM  256
#define NIN   768
#define NF    4096
#define NFH   2048
#define KSTRIDE 4104
#define PI_F  3.14159265358979323846f

// ---------------- scratch ----------------------------------------------------
__device__ float  g_WinT [DDIM * NIN];                 // tf32-rounded
__device__ float  g_WoutT[DDIM * DDIM];                // tf32-rounded
__device__ float  g_kfilt[DDIM * LSEQ];
__device__ float2 g_Kf   [DDIM * KSTRIDE];
__device__ float  g_halo [(size_t)BB * 32 * 2 * NIN];  // x at tile-boundary rows
__device__ float  g_x0t  [(size_t)BB * DDIM * LSEQ];
__device__ float  g_vint [(size_t)BB * DDIM * LSEQ];
__device__ float2 g_tw1  [1024];
__device__ float2 g_twu  [2049];

__device__ __forceinline__ float2 cmul(float2 a, float2 b) {
    return make_float2(a.x * b.x - a.y * b.y, a.x * b.y + a.y * b.x);
}

#define CPA16(dst_u32, src_ptr) \
    asm volatile("cp.async.cg.shared.global [%0], [%1], 16;" :: "r"(dst_u32), "l"(src_ptr))
#define CPA_COMMIT() asm volatile("cp.async.commit_group;")

#define MMA_TF32(C, A, B) \
    asm volatile("mma.sync.aligned.m16n8k8.row.col.f32.tf32.tf32.f32 " \
        "{%0,%1,%2,%3}, {%4,%5,%6,%7}, {%8,%9}, {%0,%1,%2,%3};" \
        : "+f"(C.x), "+f"(C.y), "+f"(C.z), "+f"(C.w) \
        : "r"(A[0]), "r"(A[1]), "r"(A[2]), "r"(A[3]), "r"(B[0]), "r"(B[1]))

__device__ __forceinline__ uint32_t f2tf32(float v) {
    uint32_t r;
    asm("cvt.rna.tf32.f32 %0, %1;" : "=r"(r) : "f"(v));
    return r;
}
__device__ __forceinline__ float tf32r(float v) { return __uint_as_float(f2tf32(v)); }

// ---------------- K0: transpose + tf32-round weights + twiddles --------------
__global__ void k_transpose(const float* __restrict__ Win, const float* __restrict__ Wout) {
    int i = blockIdx.x * blockDim.x + threadIdx.x;
    if (i < DDIM * NIN) {
        int d = i / NIN, e = i % NIN;
        g_WinT[i] = tf32r(Win[e * DDIM + d]);
    }
    int j = i - DDIM * NIN;
    if (j >= 0 && j < DDIM * DDIM) {
        int d = j / DDIM, n = j % DDIM;
        g_WoutT[j] = tf32r(Wout[n * DDIM + d]);
    }
    if (i < 1024) {
        float ang = -2.0f * PI_F * (float)i / (float)NF;
        float sn, cs; sincosf(ang, &sn, &cs);
        g_tw1[i] = make_float2(cs, sn);
    }
    if (i < 2049) {
        float ang = PI_F * (float)i / (float)NF;
        float sn, cs; sincosf(ang, &sn, &cs);
        g_twu[i] = make_float2(cs, sn);
    }
}

// ---------------- K1: implicit filter MLP (4 l per block) --------------------
__global__ void k_filter(const float* __restrict__ w1, const float* __restrict__ b1,
                         const float* __restrict__ fr,
                         const float* __restrict__ w2, const float* __restrict__ b2,
                         const float* __restrict__ w3, const float* __restrict__ b3,
                         const float* __restrict__ w4) {
    int lq = threadIdx.x >> 6;
    int j  = threadIdx.x & 63;
    int l  = blockIdx.x * 4 + lq;
    __shared__ float hA[4][64], hB[4][64];

    float t    = (float)l * (1.0f / (float)(LSEQ - 1));
    float wang = 2.0f * PI_F * (float)l / (float)LSEQ;
    const float f0 = 1e-4f;
    float z0 = t, z1 = cosf(f0 * wang), z2 = -sinf(f0 * wang);

    float a = z0 * w1[j * 3 + 0] + z1 * w1[j * 3 + 1] + z2 * w1[j * 3 + 2] + b1[j];
    hA[lq][j] = sinf(fr[j] * a);
    __syncthreads();

    float s = b2[j];
    #pragma unroll
    for (int i = 0; i < 64; i++) s += hA[lq][i] * w2[j * 64 + i];
    hB[lq][j] = sinf(fr[j] * s);
    __syncthreads();

    s = b3[j];
    #pragma unroll
    for (int i = 0; i < 64; i++) s += hB[lq][i] * w3[j * 64 + i];
    float hv = sinf(fr[j] * s);
    __syncthreads();
    hA[lq][j] = hv;
    __syncthreads();

    const float min_d = logf(0.01f) / 1.5f;
    const float max_d = logf(0.01f) / 0.3f;
    #pragma unroll
    for (int r = 0; r < 4; r++) {
        int d = j * 4 + r;
        float s4 = 0.f;
        #pragma unroll
        for (int i = 0; i < 64; i++) s4 += hA[lq][i] * w4[d * 64 + i];
        float delta = fabsf(min_d + (max_d - min_d) * ((float)d / (float)(DDIM - 1)));
        g_kfilt[d * LSEQ + l] = s4 * expf(-t * delta);
    }
}

// ---------------- K1b: boundary-row projections (halo), ILP-unrolled ---------
__global__ void k_halo(const float* __restrict__ u) {
    __shared__ float su[8][256];
    int tid = threadIdx.x;                 // 256
    int rg  = blockIdx.x;                  // 0..7
    int b   = blockIdx.y;                  // 0..15
    int e   = blockIdx.z * 256 + tid;      // 0..767

    #pragma unroll
    for (int j = 0; j < 8; j++) {
        int r = rg * 8 + j;
        int t = r >> 1, w_ = r & 1;
        int l = t * 128 - 2 + w_;
        su[j][tid] = (l >= 0) ? u[((size_t)b * LSEQ + l) * DDIM + tid] : 0.f;
    }
    __syncthreads();

    float acc[8] = {};
    #pragma unroll 2
    for (int k = 0; k < 256; k += 4) {
        float wv0 = g_WinT[(k + 0) * NIN + e];
        float wv1 = g_WinT[(k + 1) * NIN + e];
        float wv2 = g_WinT[(k + 2) * NIN + e];
        float wv3 = g_WinT[(k + 3) * NIN + e];
        #pragma unroll
        for (int j = 0; j < 8; j++) {
            acc[j] += su[j][k] * wv0 + su[j][k + 1] * wv1
                    + su[j][k + 2] * wv2 + su[j][k + 3] * wv3;
        }
    }
    #pragma unroll
    for (int j = 0; j < 8; j++) {
        int r = rg * 8 + j;
        int t = r >> 1, w_ = r & 1;
        g_halo[(((size_t)b * 32 + t) * 2 + w_) * NIN + e] = acc[j];
    }
}

// ---------------- radix-16 Stockham FFT: twiddles from L2 --------------------
#define SWIZ(a) ((a) ^ (((a) >> 4) & 15))

template<int INV>
__device__ __forceinline__ void bfly4(float2 s0, float2 s1, float2 s2, float2 s3,
                                      float2& y0, float2& y1, float2& y2, float2& y3) {
    float u0x = s0.x + s2.x, u0y = s0.y + s2.y;
    float u1x = s0.x - s2.x, u1y = s0.y - s2.y;
    float u2x = s1.x + s3.x, u2y = s1.y + s3.y;
    float u3x = s1.x - s3.x, u3y = s1.y - s3.y;
    y0 = make_float2(u0x + u2x, u0y + u2y);
    y2 = make_float2(u0x - u2x, u0y - u2y);
    if (INV) {
        y1 = make_float2(u1x - u3y, u1y + u3x);
        y3 = make_float2(u1x + u3y, u1y - u3x);
    } else {
        y1 = make_float2(u1x + u3y, u1y - u3x);
        y3 = make_float2(u1x - u3y, u1y + u3x);
    }
}

template<int INV>
__device__ __forceinline__ void fft16(float2* __restrict__ buf0, float2* __restrict__ buf1,
                                      int tid) {
    const float C8 = 0.9238795325112867f;
    const float S8 = 0.3826834323650898f;
    const float C4 = 0.7071067811865476f;
    const float sg = INV ? 1.0f : -1.0f;
    const float2 F1 = make_float2( C8, sg * S8);
    const float2 F2 = make_float2( C4, sg * C4);
    const float2 F3 = make_float2( S8, sg * C8);
    const float2 F4 = make_float2(0.f, sg * 1.f);
    const float2 F6 = make_float2(-C4, sg * C4);
    const float2 F9 = make_float2(-C8, -sg * S8);

    #pragma unroll
    for (int s = 0; s < 3; s++) {
        const int m = (s == 0) ? 1 : (s == 1) ? 16 : 256;
        const float2* src = (s == 1) ? buf1 : buf0;
        float2*       dst = (s == 1) ? buf0 : buf1;
        const bool swR = (s == 1), swW = (s == 0);

        int k  = tid & (m - 1);
        int bq = tid - k;

        float2 wa1 = __ldg(&g_tw1[bq]);
        if (INV) wa1.y = -wa1.y;

        float2 X[4][4];
        #pragma unroll
        for (int j = 0; j < 4; j++)
            #pragma unroll
            for (int r = 0; r < 4; r++) {
                int a = tid + 256 * r + 1024 * j;
                X[r][j] = src[swR ? SWIZ(a) : a];
            }

        float2 wa2 = cmul(wa1, wa1);
        float2 wa3 = cmul(wa2, wa1);
        float2 wb1 = cmul(wa2, wa2);
        float2 wb2 = cmul(wb1, wb1);
        float2 wb3 = cmul(wb2, wb1);

        float2 z[4][4];
        #pragma unroll
        for (int r = 0; r < 4; r++) {
            float2 y0, y1, y2, y3;
            bfly4<INV>(X[r][0], X[r][1], X[r][2], X[r][3], y0, y1, y2, y3);
            if (r == 1) { y1 = cmul(F1, y1); y2 = cmul(F2, y2); y3 = cmul(F3, y3); }
            if (r == 2) { y1 = cmul(F2, y1); y2 = cmul(F4, y2); y3 = cmul(F6, y3); }
            if (r == 3) { y1 = cmul(F3, y1); y2 = cmul(F6, y2); y3 = cmul(F9, y3); }
            z[r][0] = y0;
            z[r][1] = cmul(wa1, y1);
            z[r][2] = cmul(wa2, y2);
            z[r][3] = cmul(wa3, y3);
        }
        #pragma unroll
        for (int c = 0; c < 4; c++) {
            float2 y0, y1, y2, y3;
            bfly4<INV>(z[0][c], z[1][c], z[2][c], z[3][c], y0, y1, y2, y3);
            float2 o1 = cmul(wb1, y1);
            float2 o2 = cmul(wb2, y2);
            float2 o3 = cmul(wb3, y3);
            int ob = 16 * bq + m * c + k;
            int a0 = ob, a1 = ob + 4 * m, a2 = ob + 8 * m, a3 = ob + 12 * m;
            if (swW) { a0 = SWIZ(a0); a1 = SWIZ(a1); a2 = SWIZ(a2); a3 = SWIZ(a3); }
            dst[a0] = y0;
            dst[a1] = o1;
            dst[a2] = o2;
            dst[a3] = o3;
        }
        __syncthreads();
    }
}

// ---------------- K2: rfft(filter, 8192), scale folded in --------------------
extern __shared__ __align__(16) float smem_raw[];
__global__ void k_filterfft() {
    int d = blockIdx.x, tid = threadIdx.x;
    float2* bufA = (float2*)smem_raw;
    float2* bufB = bufA + NF;

    const float2* kr = (const float2*)(g_kfilt + (size_t)d * LSEQ);
    for (int n = tid; n < NFH; n += 256) bufA[n] = kr[n];
    for (int n = NFH + tid; n < NF; n += 256) bufA[n] = make_float2(0.f, 0.f);
    __syncthreads();

    fft16<0>(bufA, bufB, tid);   // result in bufB

    const float sc = 1.0f / (float)NF;
    for (int k = tid; k <= NFH; k += 256) {
        float2 Zk = bufB[k];
        float2 Zm = bufB[(NF - k) & (NF - 1)];
        float2 E  = make_float2(0.5f * (Zk.x + Zm.x), 0.5f * (Zk.y - Zm.y));
        float2 O  = make_float2(0.5f * (Zk.y + Zm.y), -0.5f * (Zk.x - Zm.x));
        float2 wu = g_twu[k];
        float2 W  = make_float2(wu.x, -wu.y);
        float2 WO = cmul(W, O);
        g_Kf[(size_t)d * KSTRIDE + k]        = make_float2(sc * (E.x + WO.x), sc * (E.y + WO.y));
        g_Kf[(size_t)d * KSTRIDE + (NF - k)] = make_float2(sc * (E.x - WO.x), sc * (-(E.y - WO.y)));
    }
}

// ---------------- K3: FUSED projection GEMM + shortconv + gates --------------
#define FP_ASTR 36
#define FP_BSTR 104
#define FP_ASZ  (128 * FP_ASTR)
#define FP_BSZ  (32 * FP_BSTR)
#define FP_SMEM ((2 * FP_ASZ + 2 * FP_BSZ) * 4)   // 63488 bytes

__global__ void __launch_bounds__(256, 2) k_projfuse(const float* __restrict__ u,
                                                     const float* __restrict__ b_in,
                                                     const float* __restrict__ short_w,
                                                     const float* __restrict__ short_b) {
    extern __shared__ float sm[];
    uint32_t smb = (uint32_t)__cvta_generic_to_shared(sm);
    const int d0   = blockIdx.x * 32;        // 8 d-blocks
    const int tile = blockIdx.y;             // 0..511
    const int b  = tile >> 5;
    const int tt = tile & 31;
    const int l0 = tt * 128;
    const size_t mrow0 = (size_t)b * LSEQ + l0;

    const int tid = threadIdx.x;
    const int lane = tid & 31;
    const int warp = tid >> 5;
    const int g = lane >> 2, tg = lane & 3;
    const int wm = (warp >> 2) * 64, wn = (warp & 3) * 24;

    float4 c[4][3];
    #pragma unroll
    for (int i = 0; i < 4; i++)
        #pragma unroll
        for (int j = 0; j < 3; j++) c[i][j] = make_float4(0.f, 0.f, 0.f, 0.f);

    #pragma unroll 1
    for (int kt = 0; kt < 8; kt++) {
        if (kt == 0) {
            #pragma unroll
            for (int i = 0; i < 4; i++) {
                int ch = tid + i * 256;
                int mm = ch >> 3, kq = (ch & 7) * 4;
                CPA16(smb + (mm * FP_ASTR + kq) * 4,
                      u + (mrow0 + mm) * DDIM + kq);
            }
            #pragma unroll
            for (int i = 0; i < 3; i++) {
                int ch = tid + i * 256;
                int kk = ch / 24, j = ch % 24;
                int s = j >> 3, q = j & 7;
                CPA16(smb + (2 * FP_ASZ + kk * FP_BSTR + s * 32 + q * 4) * 4,
                      g_WinT + (size_t)kk * NIN + s * 256 + d0 + q * 4);
            }
            CPA_COMMIT();
        }
        if (kt < 7) {
            int buf = (kt + 1) & 1;
            int kb = (kt + 1) * 32;
            #pragma unroll
            for (int i = 0; i < 4; i++) {
                int ch = tid + i * 256;
                int mm = ch >> 3, kq = (ch & 7) * 4;
                CPA16(smb + (buf * FP_ASZ + mm * FP_ASTR + kq) * 4,
                      u + (mrow0 + mm) * DDIM + kb + kq);
            }
            #pragma unroll
            for (int i = 0; i < 3; i++) {
                int ch = tid + i * 256;
                int kk = ch / 24, j = ch % 24;
                int s = j >> 3, q = j & 7;
                CPA16(smb + (2 * FP_ASZ + buf * FP_BSZ + kk * FP_BSTR + s * 32 + q * 4) * 4,
                      g_WinT + (size_t)(kb + kk) * NIN + s * 256 + d0 + q * 4);
            }
            CPA_COMMIT();
            asm volatile("cp.async.wait_group 1;");
        } else {
            asm volatile("cp.async.wait_group 0;");
        }
        __syncthreads();

        const float* A = sm + (kt & 1) * FP_ASZ;
        const float* B = sm + 2 * FP_ASZ + (kt & 1) * FP_BSZ;
        #pragma unroll
        for (int ks = 0; ks < 4; ks++) {
            int k8 = ks * 8;
            uint32_t af[4][4], bf[3][2];
            #pragma unroll
            for (int mt = 0; mt < 4; mt++) {
                int r = (wm + mt * 16 + g) * FP_ASTR + k8 + tg;
                af[mt][0] = f2tf32(A[r]);
                af[mt][1] = f2tf32(A[r + 8 * FP_ASTR]);
                af[mt][2] = f2tf32(A[r + 4]);
                af[mt][3] = f2tf32(A[r + 8 * FP_ASTR + 4]);
            }
            #pragma unroll
            for (int nt = 0; nt < 3; nt++) {
                int cb = (k8 + tg) * FP_BSTR + wn + nt * 8 + g;
                bf[nt][0] = __float_as_uint(B[cb]);
                bf[nt][1] = __float_as_uint(B[cb + 4 * FP_BSTR]);
            }
            #pragma unroll
            for (int mt = 0; mt < 4; mt++)
                #pragma unroll
                for (int nt = 0; nt < 3; nt++)
                    MMA_TF32(c[mt][nt], af[mt], bf[nt]);
        }
        __syncthreads();
    }

    // ---- stage uc tile: rows 0..1 = halo (zero for l<0), rows 2..129 = GEMM --
    if (tid < 192) {
        int r = tid / 96, col = tid % 96;
        int s = col >> 5, dc = col & 31;
        int e = s * 256 + d0 + dc;
        int l = l0 - 2 + r;
        float hv = g_halo[(((size_t)b * 32 + tt) * 2 + r) * NIN + e];
        sm[r * FP_BSTR + col] = (l >= 0) ? hv + b_in[e] : 0.f;
    }
    #pragma unroll
    for (int nt = 0; nt < 3; nt++) {
        int col = wn + nt * 8 + 2 * tg;
        int s = col >> 5, dc = col & 31;
        int e = s * 256 + d0 + dc;
        float bi0 = b_in[e], bi1 = b_in[e + 1];
        #pragma unroll
        for (int mt = 0; mt < 4; mt++) {
            int row = wm + mt * 16 + g + 2;
            sm[row * FP_BSTR + col]           = c[mt][nt].x + bi0;
            sm[row * FP_BSTR + col + 1]       = c[mt][nt].y + bi1;
            sm[(row + 8) * FP_BSTR + col]     = c[mt][nt].z + bi0;
            sm[(row + 8) * FP_BSTR + col + 1] = c[mt][nt].w + bi1;
        }
    }
    __syncthreads();

    // ---- conv3 + gates, write (b,d,l) ----
    {
        int d  = tid & 31;
        int lg = tid >> 5;
        float w[3][3], sb[3];
        #pragma unroll
        for (int s = 0; s < 3; s++) {
            int e = s * 256 + d0 + d;
            w[s][0] = short_w[e * 3 + 0];
            w[s][1] = short_w[e * 3 + 1];
            w[s][2] = short_w[e * 3 + 2];
            sb[s]   = short_b[e];
        }
        float p2[3], p1[3];
        #pragma unroll
        for (int s = 0; s < 3; s++) {
            p2[s] = sm[(lg * 16 + 0) * FP_BSTR + s * 32 + d];
            p1[s] = sm[(lg * 16 + 1) * FP_BSTR + s * 32 + d];
        }
        float4 xb[4], vb[4];
        float* xf = (float*)xb;
        float* vf = (float*)vb;
        #pragma unroll
        for (int i = 0; i < 16; i++) {
            float cv[3], cur[3];
            #pragma unroll
            for (int s = 0; s < 3; s++) {
                cur[s] = sm[(lg * 16 + i + 2) * FP_BSTR + s * 32 + d];
                cv[s]  = p2[s] * w[s][0] + p1[s] * w[s][1] + cur[s] * w[s][2] + sb[s];
                p2[s] = p1[s]; p1[s] = cur[s];
            }
            xf[i] = cv[0];
            vf[i] = cv[1] * cv[2];
        }
        size_t rowo = ((size_t)b * DDIM + d0 + d) * LSEQ + l0 + lg * 16;
        float4* xo = (float4*)(g_x0t + rowo);
        float4* vo = (float4*)(g_vint + rowo);
        #pragma unroll
        for (int q = 0; q < 4; q++) { xo[q] = xb[q]; vo[q] = vb[q]; }
    }
}

// ---------------- K5: FFT long conv per (b,d) row (64 KB smem) ---------------
__global__ void k_fftconv(const float* __restrict__ filter_bias) {
    int row = blockIdx.x;
    int tid = threadIdx.x;
    int d   = row & (DDIM - 1);

    float2* bufA = (float2*)smem_raw;
    float2* bufB = bufA + NF;

    const float2* vin2 = (const float2*)(g_vint + (size_t)row * LSEQ);
    for (int n = tid; n < NFH; n += 256) bufA[n] = vin2[n];
    for (int n = NFH + tid; n < NF; n += 256) bufA[n] = make_float2(0.f, 0.f);
    __syncthreads();

    fft16<0>(bufA, bufB, tid);     // spectrum in bufB

    const float2* Kfr = g_Kf + (size_t)d * KSTRIDE;
    for (int k = tid; k <= NFH; k += 256) {
        float2 Zk = bufB[k];
        float2 Zm = bufB[(NF - k) & (NF - 1)];
        float2 E  = make_float2(0.5f * (Zk.x + Zm.x), 0.5f * (Zk.y - Zm.y));
        float2 O  = make_float2(0.5f * (Zk.y + Zm.y), -0.5f * (Zk.x - Zm.x));
        float2 wu = g_twu[k];
        float cs = wu.x, sn = wu.y;
        float2 W  = make_float2(cs, -sn);
        float2 WO = cmul(W, O);
        float2 Xk = make_float2(E.x + WO.x, E.y + WO.y);
        float2 Xm = make_float2(E.x - WO.x, -(E.y - WO.y));
        float2 Yk = cmul(Xk, Kfr[k]);
        float2 Ym = cmul(Xm, Kfr[NF - k]);
        float2 Ep = make_float2(0.5f * (Yk.x + Ym.x), 0.5f * (Yk.y - Ym.y));
        float2 Dm = make_float2(0.5f * (Yk.x - Ym.x), 0.5f * (Yk.y + Ym.y));
        float2 Wp = make_float2(cs, sn);
        float2 Op = cmul(Wp, Dm);
        float2 Zpk = make_float2(Ep.x - Op.y, Ep.y + Op.x);
        if (k == 0) {
            bufB[0] = Zpk;
        } else {
            bufB[k]      = Zpk;
            bufB[NF - k] = make_float2(Ep.x + Op.y, Op.x - Ep.y);
        }
    }
    __syncthreads();

    fft16<1>(bufB, bufA, tid);     // time-domain in bufA

    float bias = filter_bias[d];
    const float2* x0r  = (const float2*)(g_x0t + (size_t)row * LSEQ);
    float2*       outr = (float2*)(g_vint + (size_t)row * LSEQ);
    for (int n = tid; n < NFH; n += 256) {
        float2 z   = bufA[n];
        float2 v   = vin2[n];
        float2 x0v = x0r[n];
        outr[n] = make_float2(tf32r((z.x + v.x * bias) * x0v.x),
                              tf32r((z.y + v.y * bias) * x0v.y));
    }
}

// ---------------- K6: output GEMM, tf32 mma.sync (operands pre-rounded) ------
#define OG_STR 136
#define OG_ASZ (32 * OG_STR)
#define OG_BSZ (32 * OG_STR)

__global__ void __launch_bounds__(256, 2) k_outgemm(float* __restrict__ out,
                                                    const float* __restrict__ b_out) {
    extern __shared__ float sm[];
    uint32_t smb = (uint32_t)__cvta_generic_to_shared(sm);
    const int m0 = blockIdx.y * 128;
    const int n0 = blockIdx.x * 128;
    const int b  = m0 >> 12;
    const int l0 = m0 & (LSEQ - 1);
    const int tid = threadIdx.x;
    const int lane = tid & 31;
    const int warp = tid >> 5;
    const int g = lane >> 2, tg = lane & 3;
    const int wm = (warp >> 2) * 64, wn = (warp & 3) * 32;

    float4 c[4][4];
    #pragma unroll
    for (int i = 0; i < 4; i++)
        #pragma unroll
        for (int j = 0; j < 4; j++) c[i][j] = make_float4(0.f, 0.f, 0.f, 0.f);

    #pragma unroll 1
    for (int kt = 0; kt < 8; kt++) {
        if (kt == 0) {
            #pragma unroll
            for (int i = 0; i < 4; i++) {
                int ch = tid + i * 256;
                int kk = ch >> 5, mq = (ch & 31) * 4;
                CPA16(smb + (kk * OG_STR + mq) * 4,
                      g_vint + ((size_t)b * DDIM + kk) * LSEQ + l0 + mq);
                CPA16(smb + (2 * OG_ASZ + kk * OG_STR + mq) * 4,
                      g_WoutT + (size_t)kk * DDIM + n0 + mq);
            }
            CPA_COMMIT();
        }
        if (kt < 7) {
            int buf = (kt + 1) & 1;
            int kb = (kt + 1) * 32;
            #pragma unroll
            for (int i = 0; i < 4; i++) {
                int ch = tid + i * 256;
                int kk = ch >> 5, mq = (ch & 31) * 4;
                CPA16(smb + (buf * OG_ASZ + kk * OG_STR + mq) * 4,
                      g_vint + ((size_t)b * DDIM + kb + kk) * LSEQ + l0 + mq);
                CPA16(smb + (2 * OG_ASZ + buf * OG_BSZ + kk * OG_STR + mq) * 4,
                      g_WoutT + (size_t)(kb + kk) * DDIM + n0 + mq);
            }
            CPA_COMMIT();
            asm volatile("cp.async.wait_group 1;");
        } else {
            asm volatile("cp.async.wait_group 0;");
        }
        __syncthreads();

        const float* A = sm + (kt & 1) * OG_ASZ;
        const float* B = sm + 2 * OG_ASZ + (kt & 1) * OG_BSZ;
        #pragma unroll
        for (int ks = 0; ks < 4; ks++) {
            int k8 = ks * 8;
            uint32_t af[4][4], bf[4][2];
            #pragma unroll
            for (int mt = 0; mt < 4; mt++) {
                int mrow = wm + mt * 16 + g;
                int r = (k8 + tg) * OG_STR + mrow;
                af[mt][0] = __float_as_uint(A[r]);
                af[mt][1] = __float_as_uint(A[r + 8]);
                af[mt][2] = __float_as_uint(A[r + 4 * OG_STR]);
                af[mt][3] = __float_as_uint(A[r + 4 * OG_STR + 8]);
            }
            #pragma unroll
            for (int nt = 0; nt < 4; nt++) {
                int cb = (k8 + tg) * OG_STR + wn + nt * 8 + g;
                bf[nt][0] = __float_as_uint(B[cb]);
                bf[nt][1] = __float_as_uint(B[cb + 4 * OG_STR]);
            }
            #pragma unroll
            for (int mt = 0; mt < 4; mt++)
                #pragma unroll
                for (int nt = 0; nt < 4; nt++)
                    MMA_TF32(c[mt][nt], af[mt], bf[nt]);
        }
        __syncthreads();
    }

    #pragma unroll
    for (int nt = 0; nt < 4; nt++) {
        int col = n0 + wn + nt * 8 + tg * 2;
        float2 bi = *(const float2*)(b_out + col);
        #pragma unroll
        for (int mt = 0; mt < 4; mt++) {
            int row = m0 + wm + mt * 16 + g;
            float2 v0 = make_float2(c[mt][nt].x + bi.x, c[mt][nt].y + bi.y);
            float2 v1 = make_float2(c[mt][nt].z + bi.x, c[mt][nt].w + bi.y);
            *(float2*)(out + (size_t)row * DDIM + col)       = v0;
            *(float2*)(out + (size_t)(row + 8) * DDIM + col) = v1;
        }
    }
}

// ---------------- launch ------------------------------------------------------
extern "C" void kernel_launch(void* const* d_in, const int* in_sizes, int n_in,
                              void* d_out, int out_size) {
    const float* u       = (const float*)d_in[0];
    const float* W_in    = (const float*)d_in[1];
    const float* b_in    = (const float*)d_in[2];
    const float* short_w = (const float*)d_in[3];
    const float* short_b = (const float*)d_in[4];
    const float* mlp_w1  = (const float*)d_in[5];
    const float* mlp_b1  = (const float*)d_in[6];
    const float* freq    = (const float*)d_in[7];
    const float* mlp_w2  = (const float*)d_in[8];
    const float* mlp_b2  = (const float*)d_in[9];
    const float* mlp_w3  = (const float*)d_in[10];
    const float* mlp_b3  = (const float*)d_in[11];
    const float* mlp_w4  = (const float*)d_in[12];
    const float* fbias   = (const float*)d_in[13];
    const float* W_out   = (const float*)d_in[14];
    const float* b_out   = (const float*)d_in[15];
    float* out = (float*)d_out;

    (void)in_sizes; (void)n_in; (void)out_size;

    const int smemFFT = NF * 8 * 2;                               // 65536
    const int smemOG  = (2 * OG_ASZ + 2 * OG_BSZ) * 4;
    cudaFuncSetAttribute(k_filterfft, cudaFuncAttributeMaxDynamicSharedMemorySize, smemFFT);
    cudaFuncSetAttribute(k_fftconv,   cudaFuncAttributeMaxDynamicSharedMemorySize, smemFFT);
    cudaFuncSetAttribute(k_projfuse,  cudaFuncAttributeMaxDynamicSharedMemorySize, FP_SMEM);
    cudaFuncSetAttribute(k_outgemm,   cudaFuncAttributeMaxDynamicSharedMemorySize, smemOG);

    k_transpose<<<(DDIM * NIN + DDIM * DDIM + 255) / 256, 256>>>(W_in, W_out);
    k_filter<<<LSEQ / 4, 256>>>(mlp_w1, mlp_b1, freq, mlp_w2, mlp_b2, mlp_w3, mlp_b3, mlp_w4);
    k_filterfft<<<DDIM, 256, smemFFT>>>();
    k_halo<<<dim3(8, BB, 3), 256>>>(u);
    k_projfuse<<<dim3(DDIM / 32, BB * 32), 256, FP_SMEM>>>(u, b_in, short_w, short_b);
    k_fftconv<<<BB * DDIM, 256, smemFFT>>>(fbias);
    k_outgemm<<<dim3(DDIM / 128, (BB * LSEQ) / 128), 256, smemOG>>>(out, b_out);
}

// round 16
// speedup vs baseline: 1.1181x; 1.0259x over previous
#include <cuda_runtime.h>
#include <math.h>
#include <stdint.h>

#define BB    16
#define LSEQ  4096
#define DDIM  256
#define NIN   768
#define NF    4096
#define NFH   2048
#define KSTRIDE 4104
#define PI_F  3.14159265358979323846f

// ---------------- scratch ----------------------------------------------------
__device__ float  g_WinT [DDIM * NIN];                 // tf32-rounded
__device__ float  g_WoutT[DDIM * DDIM];                // tf32-rounded
__device__ float  g_kfilt[DDIM * LSEQ];
__device__ float2 g_Kf   [DDIM * KSTRIDE];
__device__ float  g_halo [(size_t)BB * 32 * 2 * NIN];  // x at tile-boundary rows
__device__ float  g_x0t  [(size_t)BB * DDIM * LSEQ];
__device__ float  g_vint [(size_t)BB * DDIM * LSEQ];
__device__ float2 g_tw1  [1024];
__device__ float2 g_twu  [2049];

__device__ __forceinline__ float2 cmul(float2 a, float2 b) {
    return make_float2(a.x * b.x - a.y * b.y, a.x * b.y + a.y * b.x);
}

#define CPA16(dst_u32, src_ptr) \
    asm volatile("cp.async.cg.shared.global [%0], [%1], 16;" :: "r"(dst_u32), "l"(src_ptr))
#define CPA_COMMIT() asm volatile("cp.async.commit_group;")

#define MMA_TF32(C, A, B) \
    asm volatile("mma.sync.aligned.m16n8k8.row.col.f32.tf32.tf32.f32 " \
        "{%0,%1,%2,%3}, {%4,%5,%6,%7}, {%8,%9}, {%0,%1,%2,%3};" \
        : "+f"(C.x), "+f"(C.y), "+f"(C.z), "+f"(C.w) \
        : "r"(A[0]), "r"(A[1]), "r"(A[2]), "r"(A[3]), "r"(B[0]), "r"(B[1]))

__device__ __forceinline__ uint32_t f2tf32(float v) {
    uint32_t r;
    asm("cvt.rna.tf32.f32 %0, %1;" : "=r"(r) : "f"(v));
    return r;
}
__device__ __forceinline__ float tf32r(float v) { return __uint_as_float(f2tf32(v)); }

// ---------------- K0: transpose + tf32-round weights + twiddles --------------
__global__ void k_transpose(const float* __restrict__ Win, const float* __restrict__ Wout) {
    int i = blockIdx.x * blockDim.x + threadIdx.x;
    if (i < DDIM * NIN) {
        int d = i / NIN, e = i % NIN;
        g_WinT[i] = tf32r(Win[e * DDIM + d]);
    }
    int j = i - DDIM * NIN;
    if (j >= 0 && j < DDIM * DDIM) {
        int d = j / DDIM, n = j % DDIM;
        g_WoutT[j] = tf32r(Wout[n * DDIM + d]);
    }
    if (i < 1024) {
        float ang = -2.0f * PI_F * (float)i / (float)NF;
        float sn, cs; sincosf(ang, &sn, &cs);
        g_tw1[i] = make_float2(cs, sn);
    }
    if (i < 2049) {
        float ang = PI_F * (float)i / (float)NF;
        float sn, cs; sincosf(ang, &sn, &cs);
        g_twu[i] = make_float2(cs, sn);
    }
}

// ---------------- K1: implicit filter MLP (4 l per block) --------------------
__global__ void k_filter(const float* __restrict__ w1, const float* __restrict__ b1,
                         const float* __restrict__ fr,
                         const float* __restrict__ w2, const float* __restrict__ b2,
                         const float* __restrict__ w3, const float* __restrict__ b3,
                         const float* __restrict__ w4) {
    int lq = threadIdx.x >> 6;
    int j  = threadIdx.x & 63;
    int l  = blockIdx.x * 4 + lq;
    __shared__ float hA[4][64], hB[4][64];

    float t    = (float)l * (1.0f / (float)(LSEQ - 1));
    float wang = 2.0f * PI_F * (float)l / (float)LSEQ;
    const float f0 = 1e-4f;
    float z0 = t, z1 = cosf(f0 * wang), z2 = -sinf(f0 * wang);

    float a = z0 * w1[j * 3 + 0] + z1 * w1[j * 3 + 1] + z2 * w1[j * 3 + 2] + b1[j];
    hA[lq][j] = sinf(fr[j] * a);
    __syncthreads();

    float s = b2[j];
    #pragma unroll
    for (int i = 0; i < 64; i++) s += hA[lq][i] * w2[j * 64 + i];
    hB[lq][j] = sinf(fr[j] * s);
    __syncthreads();

    s = b3[j];
    #pragma unroll
    for (int i = 0; i < 64; i++) s += hB[lq][i] * w3[j * 64 + i];
    float hv = sinf(fr[j] * s);
    __syncthreads();
    hA[lq][j] = hv;
    __syncthreads();

    const float min_d = logf(0.01f) / 1.5f;
    const float max_d = logf(0.01f) / 0.3f;
    #pragma unroll
    for (int r = 0; r < 4; r++) {
        int d = j * 4 + r;
        float s4 = 0.f;
        #pragma unroll
        for (int i = 0; i < 64; i++) s4 += hA[lq][i] * w4[d * 64 + i];
        float delta = fabsf(min_d + (max_d - min_d) * ((float)d / (float)(DDIM - 1)));
        g_kfilt[d * LSEQ + l] = s4 * expf(-t * delta);
    }
}

// ---------------- K1b: boundary-row projections (halo), ILP-unrolled ---------
__global__ void k_halo(const float* __restrict__ u) {
    __shared__ float su[8][256];
    int tid = threadIdx.x;                 // 256
    int rg  = blockIdx.x;                  // 0..7
    int b   = blockIdx.y;                  // 0..15
    int e   = blockIdx.z * 256 + tid;      // 0..767

    #pragma unroll
    for (int j = 0; j < 8; j++) {
        int r = rg * 8 + j;
        int t = r >> 1, w_ = r & 1;
        int l = t * 128 - 2 + w_;
        su[j][tid] = (l >= 0) ? u[((size_t)b * LSEQ + l) * DDIM + tid] : 0.f;
    }
    __syncthreads();

    float acc[8] = {};
    #pragma unroll 2
    for (int k = 0; k < 256; k += 4) {
        float wv0 = g_WinT[(k + 0) * NIN + e];
        float wv1 = g_WinT[(k + 1) * NIN + e];
        float wv2 = g_WinT[(k + 2) * NIN + e];
        float wv3 = g_WinT[(k + 3) * NIN + e];
        #pragma unroll
        for (int j = 0; j < 8; j++) {
            acc[j] += su[j][k] * wv0 + su[j][k + 1] * wv1
                    + su[j][k + 2] * wv2 + su[j][k + 3] * wv3;
        }
    }
    #pragma unroll
    for (int j = 0; j < 8; j++) {
        int r = rg * 8 + j;
        int t = r >> 1, w_ = r & 1;
        g_halo[(((size_t)b * 32 + t) * 2 + w_) * NIN + e] = acc[j];
    }
}

// ---------------- radix-16 Stockham FFT: IN-PLACE, single 32 KB buffer -------
// Each thread holds all its 16 points in registers mid-stage; barrier between
// the read phase and the (permuted) write-back makes single-buffer safe.
#define SWIZ(a) ((a) ^ (((a) >> 4) & 15))

template<int INV>
__device__ __forceinline__ void bfly4(float2 s0, float2 s1, float2 s2, float2 s3,
                                      float2& y0, float2& y1, float2& y2, float2& y3) {
    float u0x = s0.x + s2.x, u0y = s0.y + s2.y;
    float u1x = s0.x - s2.x, u1y = s0.y - s2.y;
    float u2x = s1.x + s3.x, u2y = s1.y + s3.y;
    float u3x = s1.x - s3.x, u3y = s1.y - s3.y;
    y0 = make_float2(u0x + u2x, u0y + u2y);
    y2 = make_float2(u0x - u2x, u0y - u2y);
    if (INV) {
        y1 = make_float2(u1x - u3y, u1y + u3x);
        y3 = make_float2(u1x + u3y, u1y - u3x);
    } else {
        y1 = make_float2(u1x + u3y, u1y - u3x);
        y3 = make_float2(u1x - u3y, u1y + u3x);
    }
}

template<int INV>
__device__ __forceinline__ void fft16(float2* __restrict__ buf, int tid) {
    const float C8 = 0.9238795325112867f;
    const float S8 = 0.3826834323650898f;
    const float C4 = 0.7071067811865476f;
    const float sg = INV ? 1.0f : -1.0f;
    const float2 F1 = make_float2( C8, sg * S8);
    const float2 F2 = make_float2( C4, sg * C4);
    const float2 F3 = make_float2( S8, sg * C8);
    const float2 F4 = make_float2(0.f, sg * 1.f);
    const float2 F6 = make_float2(-C4, sg * C4);
    const float2 F9 = make_float2(-C8, -sg * S8);

    #pragma unroll
    for (int s = 0; s < 3; s++) {
        const int m = (s == 0) ? 1 : (s == 1) ? 16 : 256;
        const bool swR = (s == 1), swW = (s == 0);

        int k  = tid & (m - 1);
        int bq = tid - k;

        float2 wa1 = __ldg(&g_tw1[bq]);
        if (INV) wa1.y = -wa1.y;

        float2 X[4][4];
        #pragma unroll
        for (int j = 0; j < 4; j++)
            #pragma unroll
            for (int r = 0; r < 4; r++) {
                int a = tid + 256 * r + 1024 * j;
                X[r][j] = buf[swR ? SWIZ(a) : a];
            }

        float2 wa2 = cmul(wa1, wa1);
        float2 wa3 = cmul(wa2, wa1);
        float2 wb1 = cmul(wa2, wa2);
        float2 wb2 = cmul(wb1, wb1);
        float2 wb3 = cmul(wb2, wb1);

        float2 z[4][4];
        #pragma unroll
        for (int r = 0; r < 4; r++) {
            float2 y0, y1, y2, y3;
            bfly4<INV>(X[r][0], X[r][1], X[r][2], X[r][3], y0, y1, y2, y3);
            if (r == 1) { y1 = cmul(F1, y1); y2 = cmul(F2, y2); y3 = cmul(F3, y3); }
            if (r == 2) { y1 = cmul(F2, y1); y2 = cmul(F4, y2); y3 = cmul(F6, y3); }
            if (r == 3) { y1 = cmul(F3, y1); y2 = cmul(F6, y2); y3 = cmul(F9, y3); }
            z[r][0] = y0;
            z[r][1] = cmul(wa1, y1);
            z[r][2] = cmul(wa2, y2);
            z[r][3] = cmul(wa3, y3);
        }

        __syncthreads();   // all reads done (values live in registers)

        #pragma unroll
        for (int c = 0; c < 4; c++) {
            float2 y0, y1, y2, y3;
            bfly4<INV>(z[0][c], z[1][c], z[2][c], z[3][c], y0, y1, y2, y3);
            float2 o1 = cmul(wb1, y1);
            float2 o2 = cmul(wb2, y2);
            float2 o3 = cmul(wb3, y3);
            int ob = 16 * bq + m * c + k;
            int a0 = ob, a1 = ob + 4 * m, a2 = ob + 8 * m, a3 = ob + 12 * m;
            if (swW) { a0 = SWIZ(a0); a1 = SWIZ(a1); a2 = SWIZ(a2); a3 = SWIZ(a3); }
            buf[a0] = y0;
            buf[a1] = o1;
            buf[a2] = o2;
            buf[a3] = o3;
        }
        __syncthreads();   // writes visible before next stage reads
    }
}

// ---------------- K2: rfft(filter, 8192), scale folded in --------------------
extern __shared__ __align__(16) float smem_raw[];
__global__ void k_filterfft() {
    int d = blockIdx.x, tid = threadIdx.x;
    float2* buf = (float2*)smem_raw;

    const float2* kr = (const float2*)(g_kfilt + (size_t)d * LSEQ);
    for (int n = tid; n < NFH; n += 256) buf[n] = kr[n];
    for (int n = NFH + tid; n < NF; n += 256) buf[n] = make_float2(0.f, 0.f);
    __syncthreads();

    fft16<0>(buf, tid);

    const float sc = 1.0f / (float)NF;
    for (int k = tid; k <= NFH; k += 256) {
        float2 Zk = buf[k];
        float2 Zm = buf[(NF - k) & (NF - 1)];
        float2 E  = make_float2(0.5f * (Zk.x + Zm.x), 0.5f * (Zk.y - Zm.y));
        float2 O  = make_float2(0.5f * (Zk.y + Zm.y), -0.5f * (Zk.x - Zm.x));
        float2 wu = g_twu[k];
        float2 W  = make_float2(wu.x, -wu.y);
        float2 WO = cmul(W, O);
        g_Kf[(size_t)d * KSTRIDE + k]        = make_float2(sc * (E.x + WO.x), sc * (E.y + WO.y));
        g_Kf[(size_t)d * KSTRIDE + (NF - k)] = make_float2(sc * (E.x - WO.x), sc * (-(E.y - WO.y)));
    }
}

// ---------------- K3: FUSED projection GEMM + shortconv + gates --------------
#define FP_ASTR 36
#define FP_BSTR 104
#define FP_ASZ  (128 * FP_ASTR)
#define FP_BSZ  (32 * FP_BSTR)
#define FP_SMEM ((2 * FP_ASZ + 2 * FP_BSZ) * 4)   // 63488 bytes

__global__ void __launch_bounds__(256, 2) k_projfuse(const float* __restrict__ u,
                                                     const float* __restrict__ b_in,
                                                     const float* __restrict__ short_w,
                                                     const float* __restrict__ short_b) {
    extern __shared__ float sm[];
    uint32_t smb = (uint32_t)__cvta_generic_to_shared(sm);
    const int d0   = blockIdx.x * 32;        // 8 d-blocks
    const int tile = blockIdx.y;             // 0..511
    const int b  = tile >> 5;
    const int tt = tile & 31;
    const int l0 = tt * 128;
    const size_t mrow0 = (size_t)b * LSEQ + l0;

    const int tid = threadIdx.x;
    const int lane = tid & 31;
    const int warp = tid >> 5;
    const int g = lane >> 2, tg = lane & 3;
    const int wm = (warp >> 2) * 64, wn = (warp & 3) * 24;

    float4 c[4][3];
    #pragma unroll
    for (int i = 0; i < 4; i++)
        #pragma unroll
        for (int j = 0; j < 3; j++) c[i][j] = make_float4(0.f, 0.f, 0.f, 0.f);

    #pragma unroll 1
    for (int kt = 0; kt < 8; kt++) {
        if (kt == 0) {
            #pragma unroll
            for (int i = 0; i < 4; i++) {
                int ch = tid + i * 256;
                int mm = ch >> 3, kq = (ch & 7) * 4;
                CPA16(smb + (mm * FP_ASTR + kq) * 4,
                      u + (mrow0 + mm) * DDIM + kq);
            }
            #pragma unroll
            for (int i = 0; i < 3; i++) {
                int ch = tid + i * 256;
                int kk = ch / 24, j = ch % 24;
                int s = j >> 3, q = j & 7;
                CPA16(smb + (2 * FP_ASZ + kk * FP_BSTR + s * 32 + q * 4) * 4,
                      g_WinT + (size_t)kk * NIN + s * 256 + d0 + q * 4);
            }
            CPA_COMMIT();
        }
        if (kt < 7) {
            int buf = (kt + 1) & 1;
            int kb = (kt + 1) * 32;
            #pragma unroll
            for (int i = 0; i < 4; i++) {
                int ch = tid + i * 256;
                int mm = ch >> 3, kq = (ch & 7) * 4;
                CPA16(smb + (buf * FP_ASZ + mm * FP_ASTR + kq) * 4,
                      u + (mrow0 + mm) * DDIM + kb + kq);
            }
            #pragma unroll
            for (int i = 0; i < 3; i++) {
                int ch = tid + i * 256;
                int kk = ch / 24, j = ch % 24;
                int s = j >> 3, q = j & 7;
                CPA16(smb + (2 * FP_ASZ + buf * FP_BSZ + kk * FP_BSTR + s * 32 + q * 4) * 4,
                      g_WinT + (size_t)(kb + kk) * NIN + s * 256 + d0 + q * 4);
            }
            CPA_COMMIT();
            asm volatile("cp.async.wait_group 1;");
        } else {
            asm volatile("cp.async.wait_group 0;");
        }
        __syncthreads();

        const float* A = sm + (kt & 1) * FP_ASZ;
        const float* B = sm + 2 * FP_ASZ + (kt & 1) * FP_BSZ;
        #pragma unroll
        for (int ks = 0; ks < 4; ks++) {
            int k8 = ks * 8;
            uint32_t af[4][4], bf[3][2];
            #pragma unroll
            for (int mt = 0; mt < 4; mt++) {
                int r = (wm + mt * 16 + g) * FP_ASTR + k8 + tg;
                af[mt][0] = f2tf32(A[r]);
                af[mt][1] = f2tf32(A[r + 8 * FP_ASTR]);
                af[mt][2] = f2tf32(A[r + 4]);
                af[mt][3] = f2tf32(A[r + 8 * FP_ASTR + 4]);
            }
            #pragma unroll
            for (int nt = 0; nt < 3; nt++) {
                int cb = (k8 + tg) * FP_BSTR + wn + nt * 8 + g;
                bf[nt][0] = __float_as_uint(B[cb]);
                bf[nt][1] = __float_as_uint(B[cb + 4 * FP_BSTR]);
            }
            #pragma unroll
            for (int mt = 0; mt < 4; mt++)
                #pragma unroll
                for (int nt = 0; nt < 3; nt++)
                    MMA_TF32(c[mt][nt], af[mt], bf[nt]);
        }
        __syncthreads();
    }

    // ---- stage uc tile: rows 0..1 = halo (zero for l<0), rows 2..129 = GEMM --
    if (tid < 192) {
        int r = tid / 96, col = tid % 96;
        int s = col >> 5, dc = col & 31;
        int e = s * 256 + d0 + dc;
        int l = l0 - 2 + r;
        float hv = g_halo[(((size_t)b * 32 + tt) * 2 + r) * NIN + e];
        sm[r * FP_BSTR + col] = (l >= 0) ? hv + b_in[e] : 0.f;
    }
    #pragma unroll
    for (int nt = 0; nt < 3; nt++) {
        int col = wn + nt * 8 + 2 * tg;
        int s = col >> 5, dc = col & 31;
        int e = s * 256 + d0 + dc;
        float bi0 = b_in[e], bi1 = b_in[e + 1];
        #pragma unroll
        for (int mt = 0; mt < 4; mt++) {
            int row = wm + mt * 16 + g + 2;
            sm[row * FP_BSTR + col]           = c[mt][nt].x + bi0;
            sm[row * FP_BSTR + col + 1]       = c[mt][nt].y + bi1;
            sm[(row + 8) * FP_BSTR + col]     = c[mt][nt].z + bi0;
            sm[(row + 8) * FP_BSTR + col + 1] = c[mt][nt].w + bi1;
        }
    }
    __syncthreads();

    // ---- conv3 + gates, write (b,d,l) ----
    {
        int d  = tid & 31;
        int lg = tid >> 5;
        float w[3][3], sb[3];
        #pragma unroll
        for (int s = 0; s < 3; s++) {
            int e = s * 256 + d0 + d;
            w[s][0] = short_w[e * 3 + 0];
            w[s][1] = short_w[e * 3 + 1];
            w[s][2] = short_w[e * 3 + 2];
            sb[s]   = short_b[e];
        }
        float p2[3], p1[3];
        #pragma unroll
        for (int s = 0; s < 3; s++) {
            p2[s] = sm[(lg * 16 + 0) * FP_BSTR + s * 32 + d];
            p1[s] = sm[(lg * 16 + 1) * FP_BSTR + s * 32 + d];
        }
        float4 xb[4], vb[4];
        float* xf = (float*)xb;
        float* vf = (float*)vb;
        #pragma unroll
        for (int i = 0; i < 16; i++) {
            float cv[3], cur[3];
            #pragma unroll
            for (int s = 0; s < 3; s++) {
                cur[s] = sm[(lg * 16 + i + 2) * FP_BSTR + s * 32 + d];
                cv[s]  = p2[s] * w[s][0] + p1[s] * w[s][1] + cur[s] * w[s][2] + sb[s];
                p2[s] = p1[s]; p1[s] = cur[s];
            }
            xf[i] = cv[0];
            vf[i] = cv[1] * cv[2];
        }
        size_t rowo = ((size_t)b * DDIM + d0 + d) * LSEQ + l0 + lg * 16;
        float4* xo = (float4*)(g_x0t + rowo);
        float4* vo = (float4*)(g_vint + rowo);
        #pragma unroll
        for (int q = 0; q < 4; q++) { xo[q] = xb[q]; vo[q] = vb[q]; }
    }
}

// ---------------- K5: FFT long conv per (b,d) row (32 KB smem) ---------------
__global__ void k_fftconv(const float* __restrict__ filter_bias) {
    int row = blockIdx.x;
    int tid = threadIdx.x;
    int d   = row & (DDIM - 1);

    float2* buf = (float2*)smem_raw;

    const float2* vin2 = (const float2*)(g_vint + (size_t)row * LSEQ);
    for (int n = tid; n < NFH; n += 256) buf[n] = vin2[n];
    for (int n = NFH + tid; n < NF; n += 256) buf[n] = make_float2(0.f, 0.f);
    __syncthreads();

    fft16<0>(buf, tid);     // spectrum in buf

    const float2* Kfr = g_Kf + (size_t)d * KSTRIDE;
    for (int k = tid; k <= NFH; k += 256) {
        float2 Zk = buf[k];
        float2 Zm = buf[(NF - k) & (NF - 1)];
        float2 E  = make_float2(0.5f * (Zk.x + Zm.x), 0.5f * (Zk.y - Zm.y));
        float2 O  = make_float2(0.5f * (Zk.y + Zm.y), -0.5f * (Zk.x - Zm.x));
        float2 wu = g_twu[k];
        float cs = wu.x, sn = wu.y;
        float2 W  = make_float2(cs, -sn);
        float2 WO = cmul(W, O);
        float2 Xk = make_float2(E.x + WO.x, E.y + WO.y);
        float2 Xm = make_float2(E.x - WO.x, -(E.y - WO.y));
        float2 Yk = cmul(Xk, Kfr[k]);
        float2 Ym = cmul(Xm, Kfr[NF - k]);
        float2 Ep = make_float2(0.5f * (Yk.x + Ym.x), 0.5f * (Yk.y - Ym.y));
        float2 Dm = make_float2(0.5f * (Yk.x - Ym.x), 0.5f * (Yk.y + Ym.y));
        float2 Wp = make_float2(cs, sn);
        float2 Op = cmul(Wp, Dm);
        float2 Zpk = make_float2(Ep.x - Op.y, Ep.y + Op.x);
        if (k == 0) {
            buf[0] = Zpk;
        } else {
            buf[k]      = Zpk;
            buf[NF - k] = make_float2(Ep.x + Op.y, Op.x - Ep.y);
        }
    }
    __syncthreads();

    fft16<1>(buf, tid);     // time-domain in buf

    float bias = filter_bias[d];
    const float2* x0r  = (const float2*)(g_x0t + (size_t)row * LSEQ);
    float2*       outr = (float2*)(g_vint + (size_t)row * LSEQ);
    for (int n = tid; n < NFH; n += 256) {
        float2 z   = buf[n];
        float2 v   = vin2[n];
        float2 x0v = x0r[n];
        outr[n] = make_float2(tf32r((z.x + v.x * bias) * x0v.x),
                              tf32r((z.y + v.y * bias) * x0v.y));
    }
}

// ---------------- K6: output GEMM, tf32 mma.sync (operands pre-rounded) ------
#define OG_STR 136
#define OG_ASZ (32 * OG_STR)
#define OG_BSZ (32 * OG_STR)

__global__ void __launch_bounds__(256, 2) k_outgemm(float* __restrict__ out,
                                                    const float* __restrict__ b_out) {
    extern __shared__ float sm[];
    uint32_t smb = (uint32_t)__cvta_generic_to_shared(sm);
    const int m0 = blockIdx.y * 128;
    const int n0 = blockIdx.x * 128;
    const int b  = m0 >> 12;
    const int l0 = m0 & (LSEQ - 1);
    const int tid = threadIdx.x;
    const int lane = tid & 31;
    const int warp = tid >> 5;
    const int g = lane >> 2, tg = lane & 3;
    const int wm = (warp >> 2) * 64, wn = (warp & 3) * 32;

    float4 c[4][4];
    #pragma unroll
    for (int i = 0; i < 4; i++)
        #pragma unroll
        for (int j = 0; j < 4; j++) c[i][j] = make_float4(0.f, 0.f, 0.f, 0.f);

    #pragma unroll 1
    for (int kt = 0; kt < 8; kt++) {
        if (kt == 0) {
            #pragma unroll
            for (int i = 0; i < 4; i++) {
                int ch = tid + i * 256;
                int kk = ch >> 5, mq = (ch & 31) * 4;
                CPA16(smb + (kk * OG_STR + mq) * 4,
                      g_vint + ((size_t)b * DDIM + kk) * LSEQ + l0 + mq);
                CPA16(smb + (2 * OG_ASZ + kk * OG_STR + mq) * 4,
                      g_WoutT + (size_t)kk * DDIM + n0 + mq);
            }
            CPA_COMMIT();
        }
        if (kt < 7) {
            int buf = (kt + 1) & 1;
            int kb = (kt + 1) * 32;
            #pragma unroll
            for (int i = 0; i < 4; i++) {
                int ch = tid + i * 256;
                int kk = ch >> 5, mq = (ch & 31) * 4;
                CPA16(smb + (buf * OG_ASZ + kk * OG_STR + mq) * 4,
                      g_vint + ((size_t)b * DDIM + kb + kk) * LSEQ + l0 + mq);
                CPA16(smb + (2 * OG_ASZ + buf * OG_BSZ + kk * OG_STR + mq) * 4,
                      g_WoutT + (size_t)(kb + kk) * DDIM + n0 + mq);
            }
            CPA_COMMIT();
            asm volatile("cp.async.wait_group 1;");
        } else {
            asm volatile("cp.async.wait_group 0;");
        }
        __syncthreads();

        const float* A = sm + (kt & 1) * OG_ASZ;
        const float* B = sm + 2 * OG_ASZ + (kt & 1) * OG_BSZ;
        #pragma unroll
        for (int ks = 0; ks < 4; ks++) {
            int k8 = ks * 8;
            uint32_t af[4][4], bf[4][2];
            #pragma unroll
            for (int mt = 0; mt < 4; mt++) {
                int mrow = wm + mt * 16 + g;
                int r = (k8 + tg) * OG_STR + mrow;
                af[mt][0] = __float_as_uint(A[r]);
                af[mt][1] = __float_as_uint(A[r + 8]);
                af[mt][2] = __float_as_uint(A[r + 4 * OG_STR]);
                af[mt][3] = __float_as_uint(A[r + 4 * OG_STR + 8]);
            }
            #pragma unroll
            for (int nt = 0; nt < 4; nt++) {
                int cb = (k8 + tg) * OG_STR + wn + nt * 8 + g;
                bf[nt][0] = __float_as_uint(B[cb]);
                bf[nt][1] = __float_as_uint(B[cb + 4 * OG_STR]);
            }
            #pragma unroll
            for (int mt = 0; mt < 4; mt++)
                #pragma unroll
                for (int nt = 0; nt < 4; nt++)
                    MMA_TF32(c[mt][nt], af[mt], bf[nt]);
        }
        __syncthreads();
    }

    #pragma unroll
    for (int nt = 0; nt < 4; nt++) {
        int col = n0 + wn + nt * 8 + tg * 2;
        float2 bi = *(const float2*)(b_out + col);
        #pragma unroll
        for (int mt = 0; mt < 4; mt++) {
            int row = m0 + wm + mt * 16 + g;
            float2 v0 = make_float2(c[mt][nt].x + bi.x, c[mt][nt].y + bi.y);
            float2 v1 = make_float2(c[mt][nt].z + bi.x, c[mt][nt].w + bi.y);
            *(float2*)(out + (size_t)row * DDIM + col)       = v0;
            *(float2*)(out + (size_t)(row + 8) * DDIM + col) = v1;
        }
    }
}

// ---------------- launch ------------------------------------------------------
extern "C" void kernel_launch(void* const* d_in, const int* in_sizes, int n_in,
                              void* d_out, int out_size) {
    const float* u       = (const float*)d_in[0];
    const float* W_in    = (const float*)d_in[1];
    const float* b_in    = (const float*)d_in[2];
    const float* short_w = (const float*)d_in[3];
    const float* short_b = (const float*)d_in[4];
    const float* mlp_w1  = (const float*)d_in[5];
    const float* mlp_b1  = (const float*)d_in[6];
    const float* freq    = (const float*)d_in[7];
    const float* mlp_w2  = (const float*)d_in[8];
    const float* mlp_b2  = (const float*)d_in[9];
    const float* mlp_w3  = (const float*)d_in[10];
    const float* mlp_b3  = (const float*)d_in[11];
    const float* mlp_w4  = (const float*)d_in[12];
    const float* fbias   = (const float*)d_in[13];
    const float* W_out   = (const float*)d_in[14];
    const float* b_out   = (const float*)d_in[15];
    float* out = (float*)d_out;

    (void)in_sizes; (void)n_in; (void)out_size;

    const int smemFFT = NF * 8;                                   // 32768
    const int smemOG  = (2 * OG_ASZ + 2 * OG_BSZ) * 4;
    cudaFuncSetAttribute(k_filterfft, cudaFuncAttributeMaxDynamicSharedMemorySize, smemFFT);
    cudaFuncSetAttribute(k_fftconv,   cudaFuncAttributeMaxDynamicSharedMemorySize, smemFFT);
    cudaFuncSetAttribute(k_projfuse,  cudaFuncAttributeMaxDynamicSharedMemorySize, FP_SMEM);
    cudaFuncSetAttribute(k_outgemm,   cudaFuncAttributeMaxDynamicSharedMemorySize, smemOG);

    k_transpose<<<(DDIM * NIN + DDIM * DDIM + 255) / 256, 256>>>(W_in, W_out);
    k_filter<<<LSEQ / 4, 256>>>(mlp_w1, mlp_b1, freq, mlp_w2, mlp_b2, mlp_w3, mlp_b3, mlp_w4);
    k_filterfft<<<DDIM, 256, smemFFT>>>();
    k_halo<<<dim3(8, BB, 3), 256>>>(u);
    k_projfuse<<<dim3(DDIM / 32, BB * 32), 256, FP_SMEM>>>(u, b_in, short_w, short_b);
    k_fftconv<<<BB * DDIM, 256, smemFFT>>>(fbias);
    k_outgemm<<<dim3(DDIM / 128, (BB * LSEQ) / 128), 256, smemOG>>>(out, b_out);
}